// round 13
// baseline (speedup 1.0000x reference)
#include <cuda_runtime.h>
#include <cuda_bf16.h>
#include <math.h>
#include <stdint.h>

#define B_  128
#define T_  256
#define F_  512
#define H_  1024
#define G4  4096   // 4*H

// ---------------------------------------------------------------------------
// Scratch (static __device__; no runtime allocation)
// ---------------------------------------------------------------------------
__device__ float         g_xz[(size_t)T_ * B_ * G4];          // 537 MB fp32
__device__ float         g_c[(size_t)B_ * H_];
__device__ __nv_bfloat16 g_Ut_hi[(size_t)G4 * H_];            // U^T [4096][1024]
__device__ __nv_bfloat16 g_Ut_lo[(size_t)G4 * H_];
__device__ __nv_bfloat16 g_Wt_hi[(size_t)G4 * F_];            // W^T [4096][512]
__device__ __nv_bfloat16 g_Wt_lo[(size_t)G4 * F_];
__device__ __nv_bfloat16 g_x_hi[(size_t)B_ * T_ * F_];
__device__ __nv_bfloat16 g_x_lo[(size_t)B_ * T_ * F_];
__device__ __nv_bfloat16 g_h_hi[(size_t)B_ * H_];
__device__ __nv_bfloat16 g_h_lo[(size_t)B_ * H_];
__device__ unsigned      g_bar;

__device__ __forceinline__ float fast_sigmoid(float z) {
    return 1.0f / (1.0f + __expf(-z));
}
__device__ __forceinline__ uint32_t smem_u32(const void* p) {
    uint32_t a;
    asm("{ .reg .u64 t; cvta.to.shared.u64 t, %1; cvt.u32.u64 %0, t; }" : "=r"(a) : "l"(p));
    return a;
}

// All-scalar ldmatrix / mma macros (no array operands anywhere).
#define LDM4(r0, r1, r2, r3, addr)                                            \
    asm volatile("ldmatrix.sync.aligned.m8n8.x4.shared.b16 {%0,%1,%2,%3}, [%4];" \
                 : "=r"(r0), "=r"(r1), "=r"(r2), "=r"(r3) : "r"(addr))
#define MMA(c0, c1, c2, c3, a0, a1, a2, a3, b0, b1)                           \
    asm volatile("mma.sync.aligned.m16n8k16.row.col.f32.bf16.bf16.f32 "       \
                 "{%0,%1,%2,%3}, {%4,%5,%6,%7}, {%8,%9}, {%0,%1,%2,%3};"      \
                 : "+f"(c0), "+f"(c1), "+f"(c2), "+f"(c3)                     \
                 : "r"(a0), "r"(a1), "r"(a2), "r"(a3), "r"(b0), "r"(b1))

// smem tile: 64 bf16/row padded to 144 B -> 8 consecutive rows hit 8 distinct
// 16B banks (144 mod 128 = 16) => conflict-free ldmatrix and STS.
#define RSB   144
#define A_HI  0
#define A_LO  18432
#define B_HI  36864
#define B_LO  41472
#define SMB   46080   // <= 48 KB: static __shared__

// ---------------------------------------------------------------------------
// Prep kernels
// ---------------------------------------------------------------------------
__global__ void init_bar_kernel() { g_bar = 0u; }

__global__ void convx_kernel(const float* __restrict__ x) {
    size_t i = ((size_t)blockIdx.x * 256 + threadIdx.x) * 4;   // grid 16384
    float4 v = *(const float4*)(x + i);
    float vv[4] = {v.x, v.y, v.z, v.w};
#pragma unroll
    for (int m = 0; m < 4; m++) {
        __nv_bfloat16 hi = __float2bfloat16(vv[m]);
        g_x_hi[i + m] = hi;
        g_x_lo[i + m] = __float2bfloat16(vv[m] - __bfloat162float(hi));
    }
}

// in [K][N] fp32 -> (which ? g_Wt : g_Ut) hi/lo [N][K] bf16
__global__ __launch_bounds__(256) void transpose_split_kernel(const float* __restrict__ in,
                                                              int K, int N, int which) {
    __nv_bfloat16* ohi = which ? g_Wt_hi : g_Ut_hi;
    __nv_bfloat16* olo = which ? g_Wt_lo : g_Ut_lo;
    __shared__ float ts[32][33];
    int k0 = blockIdx.x * 32, n0 = blockIdx.y * 32;
    int r = threadIdx.x >> 5, c = threadIdx.x & 31;
#pragma unroll
    for (int i = 0; i < 4; i++)
        ts[r + i * 8][c] = in[(size_t)(k0 + r + i * 8) * N + n0 + c];
    __syncthreads();
#pragma unroll
    for (int i = 0; i < 4; i++) {
        int n = n0 + r + i * 8;
        float v = ts[c][r + i * 8];
        __nv_bfloat16 hi = __float2bfloat16(v);
        ohi[(size_t)n * K + k0 + c] = hi;
        olo[(size_t)n * K + k0 + c] = __float2bfloat16(v - __bfloat162float(hi));
    }
}

// ---------------------------------------------------------------------------
// xw MMA kernel (unchanged, proven): g_xz[t][b][n] = x_t @ W + bias.
// Grid (128, 256) = (n-tile, t). M=128, N=32/CTA, K=512.
// ---------------------------------------------------------------------------
__global__ __launch_bounds__(256) void xw_mma_kernel(const float* __restrict__ bias) {
    __shared__ __align__(16) char sm[SMB];
    const int tid = threadIdx.x, wid = tid >> 5, lane = tid & 31;
    const int n0 = blockIdx.x * 32;
    const int t  = blockIdx.y;
    const uint32_t sb = smem_u32(sm);
    const int m0 = wid * 16;

    const uint32_t a_off = (uint32_t)((m0 + (lane & 15)) * RSB + (lane >> 4) * 16);
    const uint32_t b_off = (uint32_t)((((lane >> 4) & 1) * 8 + (lane & 7)) * RSB
                                      + ((lane >> 3) & 1) * 16);

    float ci0 = 0.f, ci1 = 0.f, ci2 = 0.f, ci3 = 0.f;
    float cf0 = 0.f, cf1 = 0.f, cf2 = 0.f, cf3 = 0.f;
    float cg0 = 0.f, cg1 = 0.f, cg2 = 0.f, cg3 = 0.f;
    float co0 = 0.f, co1 = 0.f, co2 = 0.f, co3 = 0.f;

    const int ra = tid >> 3;
    const int k8 = tid & 7;
    const size_t aoff = ((size_t)ra * T_ + t) * F_ + k8 * 8;
    const size_t arow = (size_t)32 * T_ * F_;
    const size_t boff = (size_t)(n0 + ra) * F_ + k8 * 8;
    const uint32_t sa  = (uint32_t)(ra * RSB + k8 * 16);

    uint4 p0, p1, p2, p3, p4, p5, p6, p7, q0, q1;
    p0 = *(const uint4*)(g_x_hi + aoff);
    p1 = *(const uint4*)(g_x_hi + aoff + arow);
    p2 = *(const uint4*)(g_x_hi + aoff + 2 * arow);
    p3 = *(const uint4*)(g_x_hi + aoff + 3 * arow);
    p4 = *(const uint4*)(g_x_lo + aoff);
    p5 = *(const uint4*)(g_x_lo + aoff + arow);
    p6 = *(const uint4*)(g_x_lo + aoff + 2 * arow);
    p7 = *(const uint4*)(g_x_lo + aoff + 3 * arow);
    q0 = *(const uint4*)(g_Wt_hi + boff);
    q1 = *(const uint4*)(g_Wt_lo + boff);

    for (int kt = 0; kt < 8; kt++) {
        __syncthreads();
        *(uint4*)(sm + A_HI + sa)            = p0;
        *(uint4*)(sm + A_HI + sa + 32 * RSB) = p1;
        *(uint4*)(sm + A_HI + sa + 64 * RSB) = p2;
        *(uint4*)(sm + A_HI + sa + 96 * RSB) = p3;
        *(uint4*)(sm + A_LO + sa)            = p4;
        *(uint4*)(sm + A_LO + sa + 32 * RSB) = p5;
        *(uint4*)(sm + A_LO + sa + 64 * RSB) = p6;
        *(uint4*)(sm + A_LO + sa + 96 * RSB) = p7;
        *(uint4*)(sm + B_HI + sa)            = q0;
        *(uint4*)(sm + B_LO + sa)            = q1;
        __syncthreads();
        if (kt + 1 < 8) {
            const size_t ko = (size_t)(kt + 1) * 64;
            p0 = *(const uint4*)(g_x_hi + aoff + ko);
            p1 = *(const uint4*)(g_x_hi + aoff + arow + ko);
            p2 = *(const uint4*)(g_x_hi + aoff + 2 * arow + ko);
            p3 = *(const uint4*)(g_x_hi + aoff + 3 * arow + ko);
            p4 = *(const uint4*)(g_x_lo + aoff + ko);
            p5 = *(const uint4*)(g_x_lo + aoff + arow + ko);
            p6 = *(const uint4*)(g_x_lo + aoff + 2 * arow + ko);
            p7 = *(const uint4*)(g_x_lo + aoff + 3 * arow + ko);
            q0 = *(const uint4*)(g_Wt_hi + boff + ko);
            q1 = *(const uint4*)(g_Wt_lo + boff + ko);
        }
#pragma unroll
        for (int s = 0; s < 4; s++) {
            uint32_t ah0, ah1, ah2, ah3, al0, al1, al2, al3;
            uint32_t b0, b1, b2, b3, d0, d1, d2, d3;
            LDM4(ah0, ah1, ah2, ah3, sb + A_HI + a_off + s * 32);
            LDM4(al0, al1, al2, al3, sb + A_LO + a_off + s * 32);
            LDM4(b0, b1, b2, b3, sb + B_HI + b_off + s * 32);
            LDM4(d0, d1, d2, d3, sb + B_LO + b_off + s * 32);
            MMA(ci0, ci1, ci2, ci3, ah0, ah1, ah2, ah3, b0, b1);
            MMA(ci0, ci1, ci2, ci3, ah0, ah1, ah2, ah3, d0, d1);
            MMA(ci0, ci1, ci2, ci3, al0, al1, al2, al3, b0, b1);
            MMA(cf0, cf1, cf2, cf3, ah0, ah1, ah2, ah3, b2, b3);
            MMA(cf0, cf1, cf2, cf3, ah0, ah1, ah2, ah3, d2, d3);
            MMA(cf0, cf1, cf2, cf3, al0, al1, al2, al3, b2, b3);
            LDM4(b0, b1, b2, b3, sb + B_HI + b_off + 16 * RSB + s * 32);
            LDM4(d0, d1, d2, d3, sb + B_LO + b_off + 16 * RSB + s * 32);
            MMA(cg0, cg1, cg2, cg3, ah0, ah1, ah2, ah3, b0, b1);
            MMA(cg0, cg1, cg2, cg3, ah0, ah1, ah2, ah3, d0, d1);
            MMA(cg0, cg1, cg2, cg3, al0, al1, al2, al3, b0, b1);
            MMA(co0, co1, co2, co3, ah0, ah1, ah2, ah3, b2, b3);
            MMA(co0, co1, co2, co3, ah0, ah1, ah2, ah3, d2, d3);
            MMA(co0, co1, co2, co3, al0, al1, al2, al3, b2, b3);
        }
    }

    const int r = lane >> 2;
    const int cc = (lane & 3) * 2;
    float2 bv0 = *(const float2*)(bias + n0 + cc);
    float2 bv1 = *(const float2*)(bias + n0 + 8 + cc);
    float2 bv2 = *(const float2*)(bias + n0 + 16 + cc);
    float2 bv3 = *(const float2*)(bias + n0 + 24 + cc);
#pragma unroll
    for (int rh = 0; rh < 2; rh++) {
        int b = m0 + r + rh * 8;
        float* dst = g_xz + ((size_t)t * B_ + b) * G4 + n0;
        float vi0 = rh ? ci2 : ci0, vi1 = rh ? ci3 : ci1;
        float vf0 = rh ? cf2 : cf0, vf1 = rh ? cf3 : cf1;
        float vg0 = rh ? cg2 : cg0, vg1 = rh ? cg3 : cg1;
        float vo0 = rh ? co2 : co0, vo1 = rh ? co3 : co1;
        *(float2*)(dst + cc)      = make_float2(vi0 + bv0.x, vi1 + bv0.y);
        *(float2*)(dst + 8 + cc)  = make_float2(vf0 + bv1.x, vf1 + bv1.y);
        *(float2*)(dst + 16 + cc) = make_float2(vg0 + bv2.x, vg1 + bv2.y);
        *(float2*)(dst + 24 + cc) = make_float2(vo0 + bv3.x, vo1 + bv3.y);
    }
}

// ---------------------------------------------------------------------------
// Persistent recurrence: 128 CTAs x 128 threads (4 warps), warp tile 32x32
// (32 batch rows x 4 gates x 8 j). Halves per-output LDS traffic vs 16x32.
// ---------------------------------------------------------------------------
__global__ __launch_bounds__(128) void lstm_persistent(float* __restrict__ out) {
    __shared__ __align__(16) char sm[SMB];
    const int tid = threadIdx.x, wid = tid >> 5, lane = tid & 31;
    const int j0 = blockIdx.x * 8;
    const uint32_t sb = smem_u32(sm);
    const int m_w = wid * 32;

    const uint32_t a_off = (uint32_t)((m_w + (lane & 15)) * RSB + (lane >> 4) * 16);
    const uint32_t b_off = (uint32_t)((((lane >> 4) & 1) * 8 + (lane & 7)) * RSB
                                      + ((lane >> 3) & 1) * 16);

    // Global/STS indexing: 128 threads.
    const int ra = tid >> 3;               // 0..15
    const int k8 = tid & 7;
    const size_t aoff = (size_t)ra * H_ + k8 * 8;            // A rows ra + 16i
    const size_t boff0 = (size_t)((ra >> 3) * H_ + j0 + (ra & 7)) * H_ + k8 * 8;          // gates 0/1
    const size_t boff1 = (size_t)(((ra + 16) >> 3) * H_ + j0 + ((ra + 16) & 7)) * H_ + k8 * 8; // gates 2/3
    const uint32_t sa  = (uint32_t)(ra * RSB + k8 * 16);

    for (int t = 0; t < T_; t++) {
        // Accumulators: x = m-frag0 (rows m_w+0..15), y = m-frag1 (rows +16..31);
        // per m-frag: 4 gates x 4 regs.
        float x00=0.f,x01=0.f,x02=0.f,x03=0.f, x10=0.f,x11=0.f,x12=0.f,x13=0.f;
        float x20=0.f,x21=0.f,x22=0.f,x23=0.f, x30=0.f,x31=0.f,x32=0.f,x33=0.f;
        float y00=0.f,y01=0.f,y02=0.f,y03=0.f, y10=0.f,y11=0.f,y12=0.f,y13=0.f;
        float y20=0.f,y21=0.f,y22=0.f,y23=0.f, y30=0.f,y31=0.f,y32=0.f,y33=0.f;

        if (t > 0) {
            uint4 ph0, ph1, ph2, ph3, ph4, ph5, ph6, ph7;
            uint4 pl0, pl1, pl2, pl3, pl4, pl5, pl6, pl7;
            uint4 qh0, qh1, ql0, ql1;
            ph0 = *(const uint4*)(g_h_hi + aoff);
            ph1 = *(const uint4*)(g_h_hi + aoff + (size_t)16 * H_);
            ph2 = *(const uint4*)(g_h_hi + aoff + (size_t)32 * H_);
            ph3 = *(const uint4*)(g_h_hi + aoff + (size_t)48 * H_);
            ph4 = *(const uint4*)(g_h_hi + aoff + (size_t)64 * H_);
            ph5 = *(const uint4*)(g_h_hi + aoff + (size_t)80 * H_);
            ph6 = *(const uint4*)(g_h_hi + aoff + (size_t)96 * H_);
            ph7 = *(const uint4*)(g_h_hi + aoff + (size_t)112 * H_);
            pl0 = *(const uint4*)(g_h_lo + aoff);
            pl1 = *(const uint4*)(g_h_lo + aoff + (size_t)16 * H_);
            pl2 = *(const uint4*)(g_h_lo + aoff + (size_t)32 * H_);
            pl3 = *(const uint4*)(g_h_lo + aoff + (size_t)48 * H_);
            pl4 = *(const uint4*)(g_h_lo + aoff + (size_t)64 * H_);
            pl5 = *(const uint4*)(g_h_lo + aoff + (size_t)80 * H_);
            pl6 = *(const uint4*)(g_h_lo + aoff + (size_t)96 * H_);
            pl7 = *(const uint4*)(g_h_lo + aoff + (size_t)112 * H_);
            qh0 = *(const uint4*)(g_Ut_hi + boff0);
            qh1 = *(const uint4*)(g_Ut_hi + boff1);
            ql0 = *(const uint4*)(g_Ut_lo + boff0);
            ql1 = *(const uint4*)(g_Ut_lo + boff1);

            for (int kt = 0; kt < 16; kt++) {
                __syncthreads();
                *(uint4*)(sm + A_HI + sa)             = ph0;
                *(uint4*)(sm + A_HI + sa + 16 * RSB)  = ph1;
                *(uint4*)(sm + A_HI + sa + 32 * RSB)  = ph2;
                *(uint4*)(sm + A_HI + sa + 48 * RSB)  = ph3;
                *(uint4*)(sm + A_HI + sa + 64 * RSB)  = ph4;
                *(uint4*)(sm + A_HI + sa + 80 * RSB)  = ph5;
                *(uint4*)(sm + A_HI + sa + 96 * RSB)  = ph6;
                *(uint4*)(sm + A_HI + sa + 112 * RSB) = ph7;
                *(uint4*)(sm + A_LO + sa)             = pl0;
                *(uint4*)(sm + A_LO + sa + 16 * RSB)  = pl1;
                *(uint4*)(sm + A_LO + sa + 32 * RSB)  = pl2;
                *(uint4*)(sm + A_LO + sa + 48 * RSB)  = pl3;
                *(uint4*)(sm + A_LO + sa + 64 * RSB)  = pl4;
                *(uint4*)(sm + A_LO + sa + 80 * RSB)  = pl5;
                *(uint4*)(sm + A_LO + sa + 96 * RSB)  = pl6;
                *(uint4*)(sm + A_LO + sa + 112 * RSB) = pl7;
                *(uint4*)(sm + B_HI + sa)             = qh0;
                *(uint4*)(sm + B_HI + sa + 16 * RSB)  = qh1;
                *(uint4*)(sm + B_LO + sa)             = ql0;
                *(uint4*)(sm + B_LO + sa + 16 * RSB)  = ql1;
                __syncthreads();
                if (kt + 1 < 16) {
                    const size_t ko = (size_t)(kt + 1) * 64;
                    ph0 = *(const uint4*)(g_h_hi + aoff + ko);
                    ph1 = *(const uint4*)(g_h_hi + aoff + (size_t)16 * H_ + ko);
                    ph2 = *(const uint4*)(g_h_hi + aoff + (size_t)32 * H_ + ko);
                    ph3 = *(const uint4*)(g_h_hi + aoff + (size_t)48 * H_ + ko);
                    ph4 = *(const uint4*)(g_h_hi + aoff + (size_t)64 * H_ + ko);
                    ph5 = *(const uint4*)(g_h_hi + aoff + (size_t)80 * H_ + ko);
                    ph6 = *(const uint4*)(g_h_hi + aoff + (size_t)96 * H_ + ko);
                    ph7 = *(const uint4*)(g_h_hi + aoff + (size_t)112 * H_ + ko);
                    pl0 = *(const uint4*)(g_h_lo + aoff + ko);
                    pl1 = *(const uint4*)(g_h_lo + aoff + (size_t)16 * H_ + ko);
                    pl2 = *(const uint4*)(g_h_lo + aoff + (size_t)32 * H_ + ko);
                    pl3 = *(const uint4*)(g_h_lo + aoff + (size_t)48 * H_ + ko);
                    pl4 = *(const uint4*)(g_h_lo + aoff + (size_t)64 * H_ + ko);
                    pl5 = *(const uint4*)(g_h_lo + aoff + (size_t)80 * H_ + ko);
                    pl6 = *(const uint4*)(g_h_lo + aoff + (size_t)96 * H_ + ko);
                    pl7 = *(const uint4*)(g_h_lo + aoff + (size_t)112 * H_ + ko);
                    qh0 = *(const uint4*)(g_Ut_hi + boff0 + ko);
                    qh1 = *(const uint4*)(g_Ut_hi + boff1 + ko);
                    ql0 = *(const uint4*)(g_Ut_lo + boff0 + ko);
                    ql1 = *(const uint4*)(g_Ut_lo + boff1 + ko);
                }
#pragma unroll
                for (int s = 0; s < 4; s++) {
                    uint32_t ah0, ah1, ah2, ah3, ah4, ah5, ah6, ah7;
                    uint32_t al0, al1, al2, al3, al4, al5, al6, al7;
                    uint32_t bh0, bh1, bh2, bh3, bh4, bh5, bh6, bh7;
                    uint32_t bl0, bl1, bl2, bl3, bl4, bl5, bl6, bl7;
                    LDM4(ah0, ah1, ah2, ah3, sb + A_HI + a_off + s * 32);
                    LDM4(ah4, ah5, ah6, ah7, sb + A_HI + a_off + 16 * RSB + s * 32);
                    LDM4(al0, al1, al2, al3, sb + A_LO + a_off + s * 32);
                    LDM4(al4, al5, al6, al7, sb + A_LO + a_off + 16 * RSB + s * 32);
                    LDM4(bh0, bh1, bh2, bh3, sb + B_HI + b_off + s * 32);
                    LDM4(bh4, bh5, bh6, bh7, sb + B_HI + b_off + 16 * RSB + s * 32);
                    LDM4(bl0, bl1, bl2, bl3, sb + B_LO + b_off + s * 32);
                    LDM4(bl4, bl5, bl6, bl7, sb + B_LO + b_off + 16 * RSB + s * 32);
                    // m-frag 0
                    MMA(x00, x01, x02, x03, ah0, ah1, ah2, ah3, bh0, bh1);
                    MMA(x00, x01, x02, x03, ah0, ah1, ah2, ah3, bl0, bl1);
                    MMA(x00, x01, x02, x03, al0, al1, al2, al3, bh0, bh1);
                    MMA(x10, x11, x12, x13, ah0, ah1, ah2, ah3, bh2, bh3);
                    MMA(x10, x11, x12, x13, ah0, ah1, ah2, ah3, bl2, bl3);
                    MMA(x10, x11, x12, x13, al0, al1, al2, al3, bh2, bh3);
                    MMA(x20, x21, x22, x23, ah0, ah1, ah2, ah3, bh4, bh5);
                    MMA(x20, x21, x22, x23, ah0, ah1, ah2, ah3, bl4, bl5);
                    MMA(x20, x21, x22, x23, al0, al1, al2, al3, bh4, bh5);
                    MMA(x30, x31, x32, x33, ah0, ah1, ah2, ah3, bh6, bh7);
                    MMA(x30, x31, x32, x33, ah0, ah1, ah2, ah3, bl6, bl7);
                    MMA(x30, x31, x32, x33, al0, al1, al2, al3, bh6, bh7);
                    // m-frag 1
                    MMA(y00, y01, y02, y03, ah4, ah5, ah6, ah7, bh0, bh1);
                    MMA(y00, y01, y02, y03, ah4, ah5, ah6, ah7, bl0, bl1);
                    MMA(y00, y01, y02, y03, al4, al5, al6, al7, bh0, bh1);
                    MMA(y10, y11, y12, y13, ah4, ah5, ah6, ah7, bh2, bh3);
                    MMA(y10, y11, y12, y13, ah4, ah5, ah6, ah7, bl2, bl3);
                    MMA(y10, y11, y12, y13, al4, al5, al6, al7, bh2, bh3);
                    MMA(y20, y21, y22, y23, ah4, ah5, ah6, ah7, bh4, bh5);
                    MMA(y20, y21, y22, y23, ah4, ah5, ah6, ah7, bl4, bl5);
                    MMA(y20, y21, y22, y23, al4, al5, al6, al7, bh4, bh5);
                    MMA(y30, y31, y32, y33, ah4, ah5, ah6, ah7, bh6, bh7);
                    MMA(y30, y31, y32, y33, ah4, ah5, ah6, ah7, bl6, bl7);
                    MMA(y30, y31, y32, y33, al4, al5, al6, al7, bh6, bh7);
                }
            }
        }

        // Epilogue: row groups rg 0..3 -> rows m_w + (lane>>2) + 8*rg;
        // cols j = j0 + (lane&3)*2 + ch. rg0/1 = m-frag0 (x), rg2/3 = m-frag1 (y).
        const int r0j = lane >> 2;
        const int jb  = (lane & 3) * 2;
        const int first = (t == 0);
#pragma unroll
        for (int rg = 0; rg < 4; rg++) {
            int b = m_w + r0j + rg * 8;
            const float* xzp = g_xz + ((size_t)t * B_ + b) * G4 + j0 + jb;
            float2 zi2 = *(const float2*)(xzp + 0 * H_);
            float2 zf2 = *(const float2*)(xzp + 1 * H_);
            float2 zg2 = *(const float2*)(xzp + 2 * H_);
            float2 zo2 = *(const float2*)(xzp + 3 * H_);
#pragma unroll
            for (int ch = 0; ch < 2; ch++) {
                float zi, zf, zg, zo;
                if (rg == 0)      { zi = ch ? x01 : x00; zf = ch ? x11 : x10;
                                    zg = ch ? x21 : x20; zo = ch ? x31 : x30; }
                else if (rg == 1) { zi = ch ? x03 : x02; zf = ch ? x13 : x12;
                                    zg = ch ? x23 : x22; zo = ch ? x33 : x32; }
                else if (rg == 2) { zi = ch ? y01 : y00; zf = ch ? y11 : y10;
                                    zg = ch ? y21 : y20; zo = ch ? y31 : y30; }
                else              { zi = ch ? y03 : y02; zf = ch ? y13 : y12;
                                    zg = ch ? y23 : y22; zo = ch ? y33 : y32; }
                zi += ch ? zi2.y : zi2.x;
                zf += ch ? zf2.y : zf2.x;
                zg += ch ? zg2.y : zg2.x;
                zo += ch ? zo2.y : zo2.x;
                float ig = fast_sigmoid(zi);
                float fg = fast_sigmoid(zf);
                float gg = tanhf(zg);
                float og = fast_sigmoid(zo);
                size_t idx = (size_t)b * H_ + j0 + jb + ch;
                float c_old = first ? 0.0f : g_c[idx];
                float cv = fg * c_old + ig * gg;
                float hv = og * tanhf(cv);
                g_c[idx] = cv;
                out[(size_t)t * B_ * H_ + idx] = hv;
                __nv_bfloat16 hi = __float2bfloat16(hv);
                g_h_hi[idx] = hi;
                g_h_lo[idx] = __float2bfloat16(hv - __bfloat162float(hi));
            }
        }

        // Grid barrier (proven): bounded spin, release/acquire fences.
        if (t + 1 < T_) {
            __syncthreads();
            if (tid == 0) {
                __threadfence();
                atomicAdd(&g_bar, 1u);
                unsigned target = (unsigned)(t + 1) * 128u;
                volatile unsigned* vb = &g_bar;
                int spins = 0;
                while (*vb < target && spins < 2000000) { spins++; __nanosleep(60); }
            }
            __syncthreads();
            __threadfence();
        }
    }
}

// ---------------------------------------------------------------------------
extern "C" void kernel_launch(void* const* d_in, const int* in_sizes, int n_in,
                              void* d_out, int out_size) {
    const float* x = (const float*)d_in[0];   // [B, T, F]
    const float* W = (const float*)d_in[1];   // [F, 4H]
    const float* U = (const float*)d_in[2];   // [H, 4H]
    const float* b = (const float*)d_in[3];   // [4H]
    float* out = (float*)d_out;               // [T, B, H]
    (void)in_sizes; (void)n_in; (void)out_size;

    // Prep (off the serial path)
    init_bar_kernel<<<1, 1>>>();
    convx_kernel<<<16384, 256>>>(x);
    transpose_split_kernel<<<dim3(F_ / 32, G4 / 32), 256>>>(W, F_, G4, 1);
    transpose_split_kernel<<<dim3(H_ / 32, G4 / 32), 256>>>(U, H_, G4, 0);

    // Phase 1: xz = x@W + bias (tensor cores)
    xw_mma_kernel<<<dim3(128, 256), 256>>>(b);

    // Phase 2: full recurrence in ONE persistent launch
    lstm_persistent<<<128, 128>>>(out);
}

// round 14
// speedup vs baseline: 1.0154x; 1.0154x over previous
#include <cuda_runtime.h>
#include <cuda_bf16.h>
#include <math.h>
#include <stdint.h>

#define B_  128
#define T_  256
#define F_  512
#define H_  1024
#define G4  4096   // 4*H

// ---------------------------------------------------------------------------
// Scratch (static __device__; no runtime allocation)
// ---------------------------------------------------------------------------
__device__ float         g_xz[(size_t)T_ * B_ * G4];          // 537 MB fp32
__device__ float         g_c[(size_t)B_ * H_];
__device__ __nv_bfloat16 g_Ut_hi[(size_t)G4 * H_];            // U^T [4096][1024]
__device__ __nv_bfloat16 g_Ut_lo[(size_t)G4 * H_];
__device__ __nv_bfloat16 g_Wt_hi[(size_t)G4 * F_];            // W^T [4096][512]
__device__ __nv_bfloat16 g_Wt_lo[(size_t)G4 * F_];
__device__ __nv_bfloat16 g_x_hi[(size_t)B_ * T_ * F_];
__device__ __nv_bfloat16 g_x_lo[(size_t)B_ * T_ * F_];
__device__ __nv_bfloat16 g_h_hi[(size_t)B_ * H_];
__device__ __nv_bfloat16 g_h_lo[(size_t)B_ * H_];
__device__ unsigned      g_bar;

__device__ __forceinline__ float fast_sigmoid(float z) {
    return 1.0f / (1.0f + __expf(-z));
}
__device__ __forceinline__ uint32_t smem_u32(const void* p) {
    uint32_t a;
    asm("{ .reg .u64 t; cvta.to.shared.u64 t, %1; cvt.u32.u64 %0, t; }" : "=r"(a) : "l"(p));
    return a;
}

// All-scalar ldmatrix / mma macros (no array operands anywhere).
#define LDM4(r0, r1, r2, r3, addr)                                            \
    asm volatile("ldmatrix.sync.aligned.m8n8.x4.shared.b16 {%0,%1,%2,%3}, [%4];" \
                 : "=r"(r0), "=r"(r1), "=r"(r2), "=r"(r3) : "r"(addr))
#define MMA(c0, c1, c2, c3, a0, a1, a2, a3, b0, b1)                           \
    asm volatile("mma.sync.aligned.m16n8k16.row.col.f32.bf16.bf16.f32 "       \
                 "{%0,%1,%2,%3}, {%4,%5,%6,%7}, {%8,%9}, {%0,%1,%2,%3};"      \
                 : "+f"(c0), "+f"(c1), "+f"(c2), "+f"(c3)                     \
                 : "r"(a0), "r"(a1), "r"(a2), "r"(a3), "r"(b0), "r"(b1))

// smem tile: 64 bf16/row padded to 144 B -> 8 consecutive rows hit 8 distinct
// 16B banks (144 mod 128 = 16) => conflict-free ldmatrix and STS.
#define RSB   144
#define A_HI  0
#define A_LO  18432
#define B_HI  36864
#define B_LO  41472
#define SMB   46080           // one buffer
#define SMB2  (2 * SMB)       // double buffer: 92160 B dynamic smem

// ---------------------------------------------------------------------------
// Prep kernels
// ---------------------------------------------------------------------------
__global__ void init_bar_kernel() { g_bar = 0u; }

__global__ void convx_kernel(const float* __restrict__ x) {
    size_t i = ((size_t)blockIdx.x * 256 + threadIdx.x) * 4;   // grid 16384
    float4 v = *(const float4*)(x + i);
    float vv[4] = {v.x, v.y, v.z, v.w};
#pragma unroll
    for (int m = 0; m < 4; m++) {
        __nv_bfloat16 hi = __float2bfloat16(vv[m]);
        g_x_hi[i + m] = hi;
        g_x_lo[i + m] = __float2bfloat16(vv[m] - __bfloat162float(hi));
    }
}

// in [K][N] fp32 -> (which ? g_Wt : g_Ut) hi/lo [N][K] bf16
__global__ __launch_bounds__(256) void transpose_split_kernel(const float* __restrict__ in,
                                                              int K, int N, int which) {
    __nv_bfloat16* ohi = which ? g_Wt_hi : g_Ut_hi;
    __nv_bfloat16* olo = which ? g_Wt_lo : g_Ut_lo;
    __shared__ float ts[32][33];
    int k0 = blockIdx.x * 32, n0 = blockIdx.y * 32;
    int r = threadIdx.x >> 5, c = threadIdx.x & 31;
#pragma unroll
    for (int i = 0; i < 4; i++)
        ts[r + i * 8][c] = in[(size_t)(k0 + r + i * 8) * N + n0 + c];
    __syncthreads();
#pragma unroll
    for (int i = 0; i < 4; i++) {
        int n = n0 + r + i * 8;
        float v = ts[c][r + i * 8];
        __nv_bfloat16 hi = __float2bfloat16(v);
        ohi[(size_t)n * K + k0 + c] = hi;
        olo[(size_t)n * K + k0 + c] = __float2bfloat16(v - __bfloat162float(hi));
    }
}

// ---------------------------------------------------------------------------
// xw MMA kernel, double-buffered: g_xz[t][b][n] = x_t @ W + bias.
// Grid (128, 256) = (n-tile, t). M=128, N=32/CTA, K=512 (8 k-tiles).
// ---------------------------------------------------------------------------
__global__ __launch_bounds__(256) void xw_mma_kernel(const float* __restrict__ bias) {
    extern __shared__ __align__(16) char sm[];
    const int tid = threadIdx.x, wid = tid >> 5, lane = tid & 31;
    const int n0 = blockIdx.x * 32;
    const int t  = blockIdx.y;
    const uint32_t sb = smem_u32(sm);
    const int m0 = wid * 16;

    const uint32_t a_off = (uint32_t)((m0 + (lane & 15)) * RSB + (lane >> 4) * 16);
    const uint32_t b_off = (uint32_t)((((lane >> 4) & 1) * 8 + (lane & 7)) * RSB
                                      + ((lane >> 3) & 1) * 16);

    float ci0 = 0.f, ci1 = 0.f, ci2 = 0.f, ci3 = 0.f;
    float cf0 = 0.f, cf1 = 0.f, cf2 = 0.f, cf3 = 0.f;
    float cg0 = 0.f, cg1 = 0.f, cg2 = 0.f, cg3 = 0.f;
    float co0 = 0.f, co1 = 0.f, co2 = 0.f, co3 = 0.f;

    const int ra = tid >> 3;
    const int k8 = tid & 7;
    const size_t aoff = ((size_t)ra * T_ + t) * F_ + k8 * 8;
    const size_t arow = (size_t)32 * T_ * F_;
    const size_t boff = (size_t)(n0 + ra) * F_ + k8 * 8;
    const uint32_t sa  = (uint32_t)(ra * RSB + k8 * 16);

    uint4 p0, p1, p2, p3, p4, p5, p6, p7, q0, q1;
    // tile 0 -> regs
    p0 = *(const uint4*)(g_x_hi + aoff);
    p1 = *(const uint4*)(g_x_hi + aoff + arow);
    p2 = *(const uint4*)(g_x_hi + aoff + 2 * arow);
    p3 = *(const uint4*)(g_x_hi + aoff + 3 * arow);
    p4 = *(const uint4*)(g_x_lo + aoff);
    p5 = *(const uint4*)(g_x_lo + aoff + arow);
    p6 = *(const uint4*)(g_x_lo + aoff + 2 * arow);
    p7 = *(const uint4*)(g_x_lo + aoff + 3 * arow);
    q0 = *(const uint4*)(g_Wt_hi + boff);
    q1 = *(const uint4*)(g_Wt_lo + boff);
    // tile 0 -> buf0
    {
        char* cs = sm;
        *(uint4*)(cs + A_HI + sa)            = p0;
        *(uint4*)(cs + A_HI + sa + 32 * RSB) = p1;
        *(uint4*)(cs + A_HI + sa + 64 * RSB) = p2;
        *(uint4*)(cs + A_HI + sa + 96 * RSB) = p3;
        *(uint4*)(cs + A_LO + sa)            = p4;
        *(uint4*)(cs + A_LO + sa + 32 * RSB) = p5;
        *(uint4*)(cs + A_LO + sa + 64 * RSB) = p6;
        *(uint4*)(cs + A_LO + sa + 96 * RSB) = p7;
        *(uint4*)(cs + B_HI + sa)            = q0;
        *(uint4*)(cs + B_LO + sa)            = q1;
    }
    // tile 1 -> regs
    {
        const size_t ko = 64;
        p0 = *(const uint4*)(g_x_hi + aoff + ko);
        p1 = *(const uint4*)(g_x_hi + aoff + arow + ko);
        p2 = *(const uint4*)(g_x_hi + aoff + 2 * arow + ko);
        p3 = *(const uint4*)(g_x_hi + aoff + 3 * arow + ko);
        p4 = *(const uint4*)(g_x_lo + aoff + ko);
        p5 = *(const uint4*)(g_x_lo + aoff + arow + ko);
        p6 = *(const uint4*)(g_x_lo + aoff + 2 * arow + ko);
        p7 = *(const uint4*)(g_x_lo + aoff + 3 * arow + ko);
        q0 = *(const uint4*)(g_Wt_hi + boff + ko);
        q1 = *(const uint4*)(g_Wt_lo + boff + ko);
    }
    __syncthreads();

    for (int kt = 0; kt < 8; kt++) {
        const uint32_t cb = sb + (uint32_t)(kt & 1) * SMB;        // compute buffer
        char* cs = sm + ((kt & 1) ^ 1) * SMB;                     // store buffer
        if (kt + 1 < 8) {                                         // STS tile kt+1
            *(uint4*)(cs + A_HI + sa)            = p0;
            *(uint4*)(cs + A_HI + sa + 32 * RSB) = p1;
            *(uint4*)(cs + A_HI + sa + 64 * RSB) = p2;
            *(uint4*)(cs + A_HI + sa + 96 * RSB) = p3;
            *(uint4*)(cs + A_LO + sa)            = p4;
            *(uint4*)(cs + A_LO + sa + 32 * RSB) = p5;
            *(uint4*)(cs + A_LO + sa + 64 * RSB) = p6;
            *(uint4*)(cs + A_LO + sa + 96 * RSB) = p7;
            *(uint4*)(cs + B_HI + sa)            = q0;
            *(uint4*)(cs + B_LO + sa)            = q1;
        }
        if (kt + 2 < 8) {                                         // LDG tile kt+2
            const size_t ko = (size_t)(kt + 2) * 64;
            p0 = *(const uint4*)(g_x_hi + aoff + ko);
            p1 = *(const uint4*)(g_x_hi + aoff + arow + ko);
            p2 = *(const uint4*)(g_x_hi + aoff + 2 * arow + ko);
            p3 = *(const uint4*)(g_x_hi + aoff + 3 * arow + ko);
            p4 = *(const uint4*)(g_x_lo + aoff + ko);
            p5 = *(const uint4*)(g_x_lo + aoff + arow + ko);
            p6 = *(const uint4*)(g_x_lo + aoff + 2 * arow + ko);
            p7 = *(const uint4*)(g_x_lo + aoff + 3 * arow + ko);
            q0 = *(const uint4*)(g_Wt_hi + boff + ko);
            q1 = *(const uint4*)(g_Wt_lo + boff + ko);
        }
#pragma unroll
        for (int s = 0; s < 4; s++) {
            uint32_t ah0, ah1, ah2, ah3, al0, al1, al2, al3;
            uint32_t b0, b1, b2, b3, d0, d1, d2, d3;
            LDM4(ah0, ah1, ah2, ah3, cb + A_HI + a_off + s * 32);
            LDM4(al0, al1, al2, al3, cb + A_LO + a_off + s * 32);
            LDM4(b0, b1, b2, b3, cb + B_HI + b_off + s * 32);
            LDM4(d0, d1, d2, d3, cb + B_LO + b_off + s * 32);
            MMA(ci0, ci1, ci2, ci3, ah0, ah1, ah2, ah3, b0, b1);
            MMA(ci0, ci1, ci2, ci3, ah0, ah1, ah2, ah3, d0, d1);
            MMA(ci0, ci1, ci2, ci3, al0, al1, al2, al3, b0, b1);
            MMA(cf0, cf1, cf2, cf3, ah0, ah1, ah2, ah3, b2, b3);
            MMA(cf0, cf1, cf2, cf3, ah0, ah1, ah2, ah3, d2, d3);
            MMA(cf0, cf1, cf2, cf3, al0, al1, al2, al3, b2, b3);
            LDM4(b0, b1, b2, b3, cb + B_HI + b_off + 16 * RSB + s * 32);
            LDM4(d0, d1, d2, d3, cb + B_LO + b_off + 16 * RSB + s * 32);
            MMA(cg0, cg1, cg2, cg3, ah0, ah1, ah2, ah3, b0, b1);
            MMA(cg0, cg1, cg2, cg3, ah0, ah1, ah2, ah3, d0, d1);
            MMA(cg0, cg1, cg2, cg3, al0, al1, al2, al3, b0, b1);
            MMA(co0, co1, co2, co3, ah0, ah1, ah2, ah3, b2, b3);
            MMA(co0, co1, co2, co3, ah0, ah1, ah2, ah3, d2, d3);
            MMA(co0, co1, co2, co3, al0, al1, al2, al3, b2, b3);
        }
        __syncthreads();
    }

    const int r = lane >> 2;
    const int cc = (lane & 3) * 2;
    float2 bv0 = *(const float2*)(bias + n0 + cc);
    float2 bv1 = *(const float2*)(bias + n0 + 8 + cc);
    float2 bv2 = *(const float2*)(bias + n0 + 16 + cc);
    float2 bv3 = *(const float2*)(bias + n0 + 24 + cc);
#pragma unroll
    for (int rh = 0; rh < 2; rh++) {
        int b = m0 + r + rh * 8;
        float* dst = g_xz + ((size_t)t * B_ + b) * G4 + n0;
        float vi0 = rh ? ci2 : ci0, vi1 = rh ? ci3 : ci1;
        float vf0 = rh ? cf2 : cf0, vf1 = rh ? cf3 : cf1;
        float vg0 = rh ? cg2 : cg0, vg1 = rh ? cg3 : cg1;
        float vo0 = rh ? co2 : co0, vo1 = rh ? co3 : co1;
        *(float2*)(dst + cc)      = make_float2(vi0 + bv0.x, vi1 + bv0.y);
        *(float2*)(dst + 8 + cc)  = make_float2(vf0 + bv1.x, vf1 + bv1.y);
        *(float2*)(dst + 16 + cc) = make_float2(vg0 + bv2.x, vg1 + bv2.y);
        *(float2*)(dst + 24 + cc) = make_float2(vo0 + bv3.x, vo1 + bv3.y);
    }
}

// ---------------------------------------------------------------------------
// Persistent recurrence, double-buffered: 128 CTAs x 256 threads (8 warps),
// warp tile 16x32 (R12 geometry — the proven-faster one).
// ---------------------------------------------------------------------------
__global__ __launch_bounds__(256) void lstm_persistent(float* __restrict__ out) {
    extern __shared__ __align__(16) char sm[];
    const int tid = threadIdx.x, wid = tid >> 5, lane = tid & 31;
    const int j0 = blockIdx.x * 8;
    const uint32_t sb = smem_u32(sm);
    const int m0 = wid * 16;

    const uint32_t a_off = (uint32_t)((m0 + (lane & 15)) * RSB + (lane >> 4) * 16);
    const uint32_t b_off = (uint32_t)((((lane >> 4) & 1) * 8 + (lane & 7)) * RSB
                                      + ((lane >> 3) & 1) * 16);

    const int ra = tid >> 3;               // A base row / B row
    const int k8 = tid & 7;
    const size_t aoff = (size_t)ra * H_ + k8 * 8;
    const size_t boff = (size_t)((ra >> 3) * H_ + j0 + (ra & 7)) * H_ + k8 * 8;
    const uint32_t sa  = (uint32_t)(ra * RSB + k8 * 16);

    const int r = lane >> 2;
    const int cc = (lane & 3) * 2;

    for (int t = 0; t < T_; t++) {
        float ci0 = 0.f, ci1 = 0.f, ci2 = 0.f, ci3 = 0.f;
        float cf0 = 0.f, cf1 = 0.f, cf2 = 0.f, cf3 = 0.f;
        float cg0 = 0.f, cg1 = 0.f, cg2 = 0.f, cg3 = 0.f;
        float co0 = 0.f, co1 = 0.f, co2 = 0.f, co3 = 0.f;

        if (t > 0) {
            uint4 p0, p1, p2, p3, p4, p5, p6, p7, q0, q1;
            // tile 0 -> regs
            p0 = *(const uint4*)(g_h_hi + aoff);
            p1 = *(const uint4*)(g_h_hi + aoff + (size_t)32 * H_);
            p2 = *(const uint4*)(g_h_hi + aoff + (size_t)64 * H_);
            p3 = *(const uint4*)(g_h_hi + aoff + (size_t)96 * H_);
            p4 = *(const uint4*)(g_h_lo + aoff);
            p5 = *(const uint4*)(g_h_lo + aoff + (size_t)32 * H_);
            p6 = *(const uint4*)(g_h_lo + aoff + (size_t)64 * H_);
            p7 = *(const uint4*)(g_h_lo + aoff + (size_t)96 * H_);
            q0 = *(const uint4*)(g_Ut_hi + boff);
            q1 = *(const uint4*)(g_Ut_lo + boff);
            // tile 0 -> buf0
            {
                char* cs = sm;
                *(uint4*)(cs + A_HI + sa)            = p0;
                *(uint4*)(cs + A_HI + sa + 32 * RSB) = p1;
                *(uint4*)(cs + A_HI + sa + 64 * RSB) = p2;
                *(uint4*)(cs + A_HI + sa + 96 * RSB) = p3;
                *(uint4*)(cs + A_LO + sa)            = p4;
                *(uint4*)(cs + A_LO + sa + 32 * RSB) = p5;
                *(uint4*)(cs + A_LO + sa + 64 * RSB) = p6;
                *(uint4*)(cs + A_LO + sa + 96 * RSB) = p7;
                *(uint4*)(cs + B_HI + sa)            = q0;
                *(uint4*)(cs + B_LO + sa)            = q1;
            }
            // tile 1 -> regs
            {
                const size_t ko = 64;
                p0 = *(const uint4*)(g_h_hi + aoff + ko);
                p1 = *(const uint4*)(g_h_hi + aoff + (size_t)32 * H_ + ko);
                p2 = *(const uint4*)(g_h_hi + aoff + (size_t)64 * H_ + ko);
                p3 = *(const uint4*)(g_h_hi + aoff + (size_t)96 * H_ + ko);
                p4 = *(const uint4*)(g_h_lo + aoff + ko);
                p5 = *(const uint4*)(g_h_lo + aoff + (size_t)32 * H_ + ko);
                p6 = *(const uint4*)(g_h_lo + aoff + (size_t)64 * H_ + ko);
                p7 = *(const uint4*)(g_h_lo + aoff + (size_t)96 * H_ + ko);
                q0 = *(const uint4*)(g_Ut_hi + boff + ko);
                q1 = *(const uint4*)(g_Ut_lo + boff + ko);
            }
            __syncthreads();

            for (int kt = 0; kt < 16; kt++) {
                const uint32_t cb = sb + (uint32_t)(kt & 1) * SMB;
                char* cs = sm + ((kt & 1) ^ 1) * SMB;
                if (kt + 1 < 16) {
                    *(uint4*)(cs + A_HI + sa)            = p0;
                    *(uint4*)(cs + A_HI + sa + 32 * RSB) = p1;
                    *(uint4*)(cs + A_HI + sa + 64 * RSB) = p2;
                    *(uint4*)(cs + A_HI + sa + 96 * RSB) = p3;
                    *(uint4*)(cs + A_LO + sa)            = p4;
                    *(uint4*)(cs + A_LO + sa + 32 * RSB) = p5;
                    *(uint4*)(cs + A_LO + sa + 64 * RSB) = p6;
                    *(uint4*)(cs + A_LO + sa + 96 * RSB) = p7;
                    *(uint4*)(cs + B_HI + sa)            = q0;
                    *(uint4*)(cs + B_LO + sa)            = q1;
                }
                if (kt + 2 < 16) {
                    const size_t ko = (size_t)(kt + 2) * 64;
                    p0 = *(const uint4*)(g_h_hi + aoff + ko);
                    p1 = *(const uint4*)(g_h_hi + aoff + (size_t)32 * H_ + ko);
                    p2 = *(const uint4*)(g_h_hi + aoff + (size_t)64 * H_ + ko);
                    p3 = *(const uint4*)(g_h_hi + aoff + (size_t)96 * H_ + ko);
                    p4 = *(const uint4*)(g_h_lo + aoff + ko);
                    p5 = *(const uint4*)(g_h_lo + aoff + (size_t)32 * H_ + ko);
                    p6 = *(const uint4*)(g_h_lo + aoff + (size_t)64 * H_ + ko);
                    p7 = *(const uint4*)(g_h_lo + aoff + (size_t)96 * H_ + ko);
                    q0 = *(const uint4*)(g_Ut_hi + boff + ko);
                    q1 = *(const uint4*)(g_Ut_lo + boff + ko);
                }
#pragma unroll
                for (int s = 0; s < 4; s++) {
                    uint32_t ah0, ah1, ah2, ah3, al0, al1, al2, al3;
                    uint32_t b0, b1, b2, b3, d0, d1, d2, d3;
                    LDM4(ah0, ah1, ah2, ah3, cb + A_HI + a_off + s * 32);
                    LDM4(al0, al1, al2, al3, cb + A_LO + a_off + s * 32);
                    LDM4(b0, b1, b2, b3, cb + B_HI + b_off + s * 32);
                    LDM4(d0, d1, d2, d3, cb + B_LO + b_off + s * 32);
                    MMA(ci0, ci1, ci2, ci3, ah0, ah1, ah2, ah3, b0, b1);
                    MMA(ci0, ci1, ci2, ci3, ah0, ah1, ah2, ah3, d0, d1);
                    MMA(ci0, ci1, ci2, ci3, al0, al1, al2, al3, b0, b1);
                    MMA(cf0, cf1, cf2, cf3, ah0, ah1, ah2, ah3, b2, b3);
                    MMA(cf0, cf1, cf2, cf3, ah0, ah1, ah2, ah3, d2, d3);
                    MMA(cf0, cf1, cf2, cf3, al0, al1, al2, al3, b2, b3);
                    LDM4(b0, b1, b2, b3, cb + B_HI + b_off + 16 * RSB + s * 32);
                    LDM4(d0, d1, d2, d3, cb + B_LO + b_off + 16 * RSB + s * 32);
                    MMA(cg0, cg1, cg2, cg3, ah0, ah1, ah2, ah3, b0, b1);
                    MMA(cg0, cg1, cg2, cg3, ah0, ah1, ah2, ah3, d0, d1);
                    MMA(cg0, cg1, cg2, cg3, al0, al1, al2, al3, b0, b1);
                    MMA(co0, co1, co2, co3, ah0, ah1, ah2, ah3, b2, b3);
                    MMA(co0, co1, co2, co3, ah0, ah1, ah2, ah3, d2, d3);
                    MMA(co0, co1, co2, co3, al0, al1, al2, al3, b2, b3);
                }
                __syncthreads();
            }
        }

        // Gates + state update (R12 epilogue, proven)
        const int first = (t == 0);
#pragma unroll
        for (int rh = 0; rh < 2; rh++) {
            int b = m0 + r + rh * 8;
            const float* xzp = g_xz + ((size_t)t * B_ + b) * G4;
#pragma unroll
            for (int ch = 0; ch < 2; ch++) {
                int j = j0 + cc + ch;
                float zi, zf, zg, zo;
                if (rh == 0 && ch == 0) { zi = ci0; zf = cf0; zg = cg0; zo = co0; }
                else if (rh == 0)       { zi = ci1; zf = cf1; zg = cg1; zo = co1; }
                else if (ch == 0)       { zi = ci2; zf = cf2; zg = cg2; zo = co2; }
                else                    { zi = ci3; zf = cf3; zg = cg3; zo = co3; }
                zi += xzp[0 * H_ + j];
                zf += xzp[1 * H_ + j];
                zg += xzp[2 * H_ + j];
                zo += xzp[3 * H_ + j];
                float ig = fast_sigmoid(zi);
                float fg = fast_sigmoid(zf);
                float gg = tanhf(zg);
                float og = fast_sigmoid(zo);
                size_t idx = (size_t)b * H_ + j;
                float c_old = first ? 0.0f : g_c[idx];
                float cv = fg * c_old + ig * gg;
                float hv = og * tanhf(cv);
                g_c[idx] = cv;
                out[(size_t)t * B_ * H_ + idx] = hv;
                __nv_bfloat16 hi = __float2bfloat16(hv);
                g_h_hi[idx] = hi;
                g_h_lo[idx] = __float2bfloat16(hv - __bfloat162float(hi));
            }
        }

        // Grid barrier (proven): bounded spin, release/acquire fences.
        if (t + 1 < T_) {
            __syncthreads();
            if (tid == 0) {
                __threadfence();
                atomicAdd(&g_bar, 1u);
                unsigned target = (unsigned)(t + 1) * 128u;
                volatile unsigned* vb = &g_bar;
                int spins = 0;
                while (*vb < target && spins < 2000000) { spins++; __nanosleep(60); }
            }
            __syncthreads();
            __threadfence();
        }
    }
}

// ---------------------------------------------------------------------------
extern "C" void kernel_launch(void* const* d_in, const int* in_sizes, int n_in,
                              void* d_out, int out_size) {
    const float* x = (const float*)d_in[0];   // [B, T, F]
    const float* W = (const float*)d_in[1];   // [F, 4H]
    const float* U = (const float*)d_in[2];   // [H, 4H]
    const float* b = (const float*)d_in[3];   // [4H]
    float* out = (float*)d_out;               // [T, B, H]
    (void)in_sizes; (void)n_in; (void)out_size;

    cudaFuncSetAttribute(xw_mma_kernel,   cudaFuncAttributeMaxDynamicSharedMemorySize, SMB2);
    cudaFuncSetAttribute(lstm_persistent, cudaFuncAttributeMaxDynamicSharedMemorySize, SMB2);

    // Prep (off the serial path)
    init_bar_kernel<<<1, 1>>>();
    convx_kernel<<<16384, 256>>>(x);
    transpose_split_kernel<<<dim3(F_ / 32, G4 / 32), 256>>>(W, F_, G4, 1);
    transpose_split_kernel<<<dim3(H_ / 32, G4 / 32), 256>>>(U, H_, G4, 0);

    // Phase 1: xz = x@W + bias (tensor cores, double-buffered)
    xw_mma_kernel<<<dim3(128, 256), 256, SMB2>>>(b);

    // Phase 2: full recurrence in ONE persistent launch (double-buffered)
    lstm_persistent<<<128, 256, SMB2>>>(out);
}

// round 15
// speedup vs baseline: 1.0650x; 1.0488x over previous
#include <cuda_runtime.h>
#include <cuda_bf16.h>
#include <math.h>
#include <stdint.h>

#define B_  128
#define T_  256
#define F_  512
#define H_  1024
#define G4  4096   // 4*H

// ---------------------------------------------------------------------------
// Scratch (static __device__; no runtime allocation)
// ---------------------------------------------------------------------------
__device__ float         g_xz[(size_t)T_ * B_ * G4];          // 537 MB fp32
__device__ float         g_c[(size_t)B_ * H_];
__device__ __nv_bfloat16 g_Ut_hi[(size_t)G4 * H_];            // U^T [4096][1024]
__device__ __nv_bfloat16 g_Ut_lo[(size_t)G4 * H_];
__device__ __nv_bfloat16 g_Wt_hi[(size_t)G4 * F_];            // W^T [4096][512]
__device__ __nv_bfloat16 g_Wt_lo[(size_t)G4 * F_];
__device__ __nv_bfloat16 g_x_hi[(size_t)B_ * T_ * F_];
__device__ __nv_bfloat16 g_x_lo[(size_t)B_ * T_ * F_];
__device__ __nv_bfloat16 g_h_hi[(size_t)B_ * H_];
__device__ __nv_bfloat16 g_h_lo[(size_t)B_ * H_];
__device__ unsigned      g_bar;

__device__ __forceinline__ float fast_sigmoid(float z) {
    return 1.0f / (1.0f + __expf(-z));
}
__device__ __forceinline__ uint32_t smem_u32(const void* p) {
    uint32_t a;
    asm("{ .reg .u64 t; cvta.to.shared.u64 t, %1; cvt.u32.u64 %0, t; }" : "=r"(a) : "l"(p));
    return a;
}

// All-scalar ldmatrix / mma macros (asm operands must be scalars, never arrays).
#define LDM4(r0, r1, r2, r3, addr)                                            \
    asm volatile("ldmatrix.sync.aligned.m8n8.x4.shared.b16 {%0,%1,%2,%3}, [%4];" \
                 : "=r"(r0), "=r"(r1), "=r"(r2), "=r"(r3) : "r"(addr))
#define MMA(c0, c1, c2, c3, a0, a1, a2, a3, b0, b1)                           \
    asm volatile("mma.sync.aligned.m16n8k16.row.col.f32.bf16.bf16.f32 "       \
                 "{%0,%1,%2,%3}, {%4,%5,%6,%7}, {%8,%9}, {%0,%1,%2,%3};"      \
                 : "+f"(c0), "+f"(c1), "+f"(c2), "+f"(c3)                     \
                 : "r"(a0), "r"(a1), "r"(a2), "r"(a3), "r"(b0), "r"(b1))

// smem tile: 64 bf16/row padded to 144 B -> 8 consecutive rows hit 8 distinct
// 16B banks (144 mod 128 = 16) => conflict-free ldmatrix and STS.
#define RSB   144

// ---- xw kernel smem layout (single buffer, N=64): 55296 B dynamic ----
#define XW_AHI  0
#define XW_ALO  18432
#define XW_BHI  36864
#define XW_BLO  46080
#define XW_SMEM 55296

// ---- step kernel smem layout: A double-buffered + U persistent: 221184 B ----
#define ST_A0   0          // buffer 0: A_HI @ +0, A_LO @ +18432
#define ST_A1   36864      // buffer 1
#define ST_AHI  0
#define ST_ALO  18432
#define ST_UHI  73728      // 16 k-tiles x 4608 B
#define ST_ULO  147456
#define ST_SMEM 221184

// ---------------------------------------------------------------------------
// Prep kernels
// ---------------------------------------------------------------------------
__global__ void init_bar_kernel() { g_bar = 0u; }

__global__ void convx_kernel(const float* __restrict__ x) {
    size_t i = ((size_t)blockIdx.x * 256 + threadIdx.x) * 4;   // grid 16384
    float4 v = *(const float4*)(x + i);
    float vv[4] = {v.x, v.y, v.z, v.w};
#pragma unroll
    for (int m = 0; m < 4; m++) {
        __nv_bfloat16 hi = __float2bfloat16(vv[m]);
        g_x_hi[i + m] = hi;
        g_x_lo[i + m] = __float2bfloat16(vv[m] - __bfloat162float(hi));
    }
}

// in [K][N] fp32 -> (which ? g_Wt : g_Ut) hi/lo [N][K] bf16
__global__ __launch_bounds__(256) void transpose_split_kernel(const float* __restrict__ in,
                                                              int K, int N, int which) {
    __nv_bfloat16* ohi = which ? g_Wt_hi : g_Ut_hi;
    __nv_bfloat16* olo = which ? g_Wt_lo : g_Ut_lo;
    __shared__ float ts[32][33];
    int k0 = blockIdx.x * 32, n0 = blockIdx.y * 32;
    int r = threadIdx.x >> 5, c = threadIdx.x & 31;
#pragma unroll
    for (int i = 0; i < 4; i++)
        ts[r + i * 8][c] = in[(size_t)(k0 + r + i * 8) * N + n0 + c];
    __syncthreads();
#pragma unroll
    for (int i = 0; i < 4; i++) {
        int n = n0 + r + i * 8;
        float v = ts[c][r + i * 8];
        __nv_bfloat16 hi = __float2bfloat16(v);
        ohi[(size_t)n * K + k0 + c] = hi;
        olo[(size_t)n * K + k0 + c] = __float2bfloat16(v - __bfloat162float(hi));
    }
}

// ---------------------------------------------------------------------------
// xw MMA kernel: g_xz[t][b][n] = x_t @ W + bias. Grid (64, 256) = (n-tile, t).
// M=128, N=64/CTA, K=512 (8 k-tiles). Single-buffered (R12-proven pattern).
// ---------------------------------------------------------------------------
__global__ __launch_bounds__(256) void xw_mma_kernel(const float* __restrict__ bias) {
    extern __shared__ __align__(16) char sm[];
    const int tid = threadIdx.x, wid = tid >> 5, lane = tid & 31;
    const int n0 = blockIdx.x * 64;
    const int t  = blockIdx.y;
    const uint32_t sb = smem_u32(sm);
    const int m0 = wid * 16;

    const uint32_t a_off = (uint32_t)((m0 + (lane & 15)) * RSB + (lane >> 4) * 16);
    const uint32_t b_off = (uint32_t)((((lane >> 4) & 1) * 8 + (lane & 7)) * RSB
                                      + ((lane >> 3) & 1) * 16);

    // 32 accumulators: n-col blocks 0..7 (8 cols each): ci,cf,cg,co,ki,kf,kg,ko
    float ci0=0.f,ci1=0.f,ci2=0.f,ci3=0.f, cf0=0.f,cf1=0.f,cf2=0.f,cf3=0.f;
    float cg0=0.f,cg1=0.f,cg2=0.f,cg3=0.f, co0=0.f,co1=0.f,co2=0.f,co3=0.f;
    float ki0=0.f,ki1=0.f,ki2=0.f,ki3=0.f, kf0=0.f,kf1=0.f,kf2=0.f,kf3=0.f;
    float kg0=0.f,kg1=0.f,kg2=0.f,kg3=0.f, ko0=0.f,ko1=0.f,ko2=0.f,ko3=0.f;

    const int ra = tid >> 3;                 // 0..31
    const int k8 = tid & 7;
    const size_t aoff = ((size_t)ra * T_ + t) * F_ + k8 * 8;
    const size_t arow = (size_t)32 * T_ * F_;
    const size_t boffA = (size_t)(n0 + ra) * F_ + k8 * 8;        // B rows 0..31
    const size_t boffB = (size_t)(n0 + 32 + ra) * F_ + k8 * 8;   // B rows 32..63
    const uint32_t sa  = (uint32_t)(ra * RSB + k8 * 16);

    uint4 p0, p1, p2, p3, p4, p5, p6, p7, q0, q1, q2, q3;
    // tile 0 -> regs
    p0 = *(const uint4*)(g_x_hi + aoff);
    p1 = *(const uint4*)(g_x_hi + aoff + arow);
    p2 = *(const uint4*)(g_x_hi + aoff + 2 * arow);
    p3 = *(const uint4*)(g_x_hi + aoff + 3 * arow);
    p4 = *(const uint4*)(g_x_lo + aoff);
    p5 = *(const uint4*)(g_x_lo + aoff + arow);
    p6 = *(const uint4*)(g_x_lo + aoff + 2 * arow);
    p7 = *(const uint4*)(g_x_lo + aoff + 3 * arow);
    q0 = *(const uint4*)(g_Wt_hi + boffA);
    q1 = *(const uint4*)(g_Wt_hi + boffB);
    q2 = *(const uint4*)(g_Wt_lo + boffA);
    q3 = *(const uint4*)(g_Wt_lo + boffB);

    for (int kt = 0; kt < 8; kt++) {
        __syncthreads();
        *(uint4*)(sm + XW_AHI + sa)            = p0;
        *(uint4*)(sm + XW_AHI + sa + 32 * RSB) = p1;
        *(uint4*)(sm + XW_AHI + sa + 64 * RSB) = p2;
        *(uint4*)(sm + XW_AHI + sa + 96 * RSB) = p3;
        *(uint4*)(sm + XW_ALO + sa)            = p4;
        *(uint4*)(sm + XW_ALO + sa + 32 * RSB) = p5;
        *(uint4*)(sm + XW_ALO + sa + 64 * RSB) = p6;
        *(uint4*)(sm + XW_ALO + sa + 96 * RSB) = p7;
        *(uint4*)(sm + XW_BHI + sa)            = q0;
        *(uint4*)(sm + XW_BHI + sa + 32 * RSB) = q1;
        *(uint4*)(sm + XW_BLO + sa)            = q2;
        *(uint4*)(sm + XW_BLO + sa + 32 * RSB) = q3;
        __syncthreads();
        if (kt + 1 < 8) {
            const size_t koff = (size_t)(kt + 1) * 64;
            p0 = *(const uint4*)(g_x_hi + aoff + koff);
            p1 = *(const uint4*)(g_x_hi + aoff + arow + koff);
            p2 = *(const uint4*)(g_x_hi + aoff + 2 * arow + koff);
            p3 = *(const uint4*)(g_x_hi + aoff + 3 * arow + koff);
            p4 = *(const uint4*)(g_x_lo + aoff + koff);
            p5 = *(const uint4*)(g_x_lo + aoff + arow + koff);
            p6 = *(const uint4*)(g_x_lo + aoff + 2 * arow + koff);
            p7 = *(const uint4*)(g_x_lo + aoff + 3 * arow + koff);
            q0 = *(const uint4*)(g_Wt_hi + boffA + koff);
            q1 = *(const uint4*)(g_Wt_hi + boffB + koff);
            q2 = *(const uint4*)(g_Wt_lo + boffA + koff);
            q3 = *(const uint4*)(g_Wt_lo + boffB + koff);
        }
#pragma unroll
        for (int s = 0; s < 4; s++) {
            uint32_t ah0, ah1, ah2, ah3, al0, al1, al2, al3;
            uint32_t b0, b1, b2, b3, d0, d1, d2, d3;
            LDM4(ah0, ah1, ah2, ah3, sb + XW_AHI + a_off + s * 32);
            LDM4(al0, al1, al2, al3, sb + XW_ALO + a_off + s * 32);
            // block 0: B rows 0-15 -> ci (cols 0-7), cf (8-15)
            LDM4(b0, b1, b2, b3, sb + XW_BHI + b_off + s * 32);
            LDM4(d0, d1, d2, d3, sb + XW_BLO + b_off + s * 32);
            MMA(ci0, ci1, ci2, ci3, ah0, ah1, ah2, ah3, b0, b1);
            MMA(ci0, ci1, ci2, ci3, ah0, ah1, ah2, ah3, d0, d1);
            MMA(ci0, ci1, ci2, ci3, al0, al1, al2, al3, b0, b1);
            MMA(cf0, cf1, cf2, cf3, ah0, ah1, ah2, ah3, b2, b3);
            MMA(cf0, cf1, cf2, cf3, ah0, ah1, ah2, ah3, d2, d3);
            MMA(cf0, cf1, cf2, cf3, al0, al1, al2, al3, b2, b3);
            // block 1: rows 16-31 -> cg (16-23), co (24-31)
            LDM4(b0, b1, b2, b3, sb + XW_BHI + b_off + 2304 + s * 32);
            LDM4(d0, d1, d2, d3, sb + XW_BLO + b_off + 2304 + s * 32);
            MMA(cg0, cg1, cg2, cg3, ah0, ah1, ah2, ah3, b0, b1);
            MMA(cg0, cg1, cg2, cg3, ah0, ah1, ah2, ah3, d0, d1);
            MMA(cg0, cg1, cg2, cg3, al0, al1, al2, al3, b0, b1);
            MMA(co0, co1, co2, co3, ah0, ah1, ah2, ah3, b2, b3);
            MMA(co0, co1, co2, co3, ah0, ah1, ah2, ah3, d2, d3);
            MMA(co0, co1, co2, co3, al0, al1, al2, al3, b2, b3);
            // block 2: rows 32-47 -> ki (32-39), kf (40-47)
            LDM4(b0, b1, b2, b3, sb + XW_BHI + b_off + 4608 + s * 32);
            LDM4(d0, d1, d2, d3, sb + XW_BLO + b_off + 4608 + s * 32);
            MMA(ki0, ki1, ki2, ki3, ah0, ah1, ah2, ah3, b0, b1);
            MMA(ki0, ki1, ki2, ki3, ah0, ah1, ah2, ah3, d0, d1);
            MMA(ki0, ki1, ki2, ki3, al0, al1, al2, al3, b0, b1);
            MMA(kf0, kf1, kf2, kf3, ah0, ah1, ah2, ah3, b2, b3);
            MMA(kf0, kf1, kf2, kf3, ah0, ah1, ah2, ah3, d2, d3);
            MMA(kf0, kf1, kf2, kf3, al0, al1, al2, al3, b2, b3);
            // block 3: rows 48-63 -> kg (48-55), ko (56-63)
            LDM4(b0, b1, b2, b3, sb + XW_BHI + b_off + 6912 + s * 32);
            LDM4(d0, d1, d2, d3, sb + XW_BLO + b_off + 6912 + s * 32);
            MMA(kg0, kg1, kg2, kg3, ah0, ah1, ah2, ah3, b0, b1);
            MMA(kg0, kg1, kg2, kg3, ah0, ah1, ah2, ah3, d0, d1);
            MMA(kg0, kg1, kg2, kg3, al0, al1, al2, al3, b0, b1);
            MMA(ko0, ko1, ko2, ko3, ah0, ah1, ah2, ah3, b2, b3);
            MMA(ko0, ko1, ko2, ko3, ah0, ah1, ah2, ah3, d2, d3);
            MMA(ko0, ko1, ko2, ko3, al0, al1, al2, al3, b2, b3);
        }
    }

    const int r = lane >> 2;
    const int cc = (lane & 3) * 2;
    float2 bv0 = *(const float2*)(bias + n0 + cc);
    float2 bv1 = *(const float2*)(bias + n0 + 8 + cc);
    float2 bv2 = *(const float2*)(bias + n0 + 16 + cc);
    float2 bv3 = *(const float2*)(bias + n0 + 24 + cc);
    float2 bv4 = *(const float2*)(bias + n0 + 32 + cc);
    float2 bv5 = *(const float2*)(bias + n0 + 40 + cc);
    float2 bv6 = *(const float2*)(bias + n0 + 48 + cc);
    float2 bv7 = *(const float2*)(bias + n0 + 56 + cc);
#pragma unroll
    for (int rh = 0; rh < 2; rh++) {
        int b = m0 + r + rh * 8;
        float* dst = g_xz + ((size_t)t * B_ + b) * G4 + n0;
        float vi0 = rh ? ci2 : ci0, vi1 = rh ? ci3 : ci1;
        float vf0 = rh ? cf2 : cf0, vf1 = rh ? cf3 : cf1;
        float vg0 = rh ? cg2 : cg0, vg1 = rh ? cg3 : cg1;
        float vo0 = rh ? co2 : co0, vo1 = rh ? co3 : co1;
        float wi0 = rh ? ki2 : ki0, wi1 = rh ? ki3 : ki1;
        float wf0 = rh ? kf2 : kf0, wf1 = rh ? kf3 : kf1;
        float wg0 = rh ? kg2 : kg0, wg1 = rh ? kg3 : kg1;
        float wo0 = rh ? ko2 : ko0, wo1 = rh ? ko3 : ko1;
        *(float2*)(dst + cc)      = make_float2(vi0 + bv0.x, vi1 + bv0.y);
        *(float2*)(dst + 8 + cc)  = make_float2(vf0 + bv1.x, vf1 + bv1.y);
        *(float2*)(dst + 16 + cc) = make_float2(vg0 + bv2.x, vg1 + bv2.y);
        *(float2*)(dst + 24 + cc) = make_float2(vo0 + bv3.x, vo1 + bv3.y);
        *(float2*)(dst + 32 + cc) = make_float2(wi0 + bv4.x, wi1 + bv4.y);
        *(float2*)(dst + 40 + cc) = make_float2(wf0 + bv5.x, wf1 + bv5.y);
        *(float2*)(dst + 48 + cc) = make_float2(wg0 + bv6.x, wg1 + bv6.y);
        *(float2*)(dst + 56 + cc) = make_float2(wo0 + bv7.x, wo1 + bv7.y);
    }
}

// ---------------------------------------------------------------------------
// Persistent recurrence: 128 CTAs x 256 threads, warp tile 16x32 (R12 proven).
// U slice resident in smem for the whole kernel; A (h) double-buffered;
// xz epilogue operands prefetched at t start.
// ---------------------------------------------------------------------------
__global__ __launch_bounds__(256) void lstm_persistent(float* __restrict__ out) {
    extern __shared__ __align__(16) char sm[];
    const int tid = threadIdx.x, wid = tid >> 5, lane = tid & 31;
    const int j0 = blockIdx.x * 8;
    const uint32_t sb = smem_u32(sm);
    const int m0 = wid * 16;

    const uint32_t a_off = (uint32_t)((m0 + (lane & 15)) * RSB + (lane >> 4) * 16);
    const uint32_t b_off = (uint32_t)((((lane >> 4) & 1) * 8 + (lane & 7)) * RSB
                                      + ((lane >> 3) & 1) * 16);

    const int ra = tid >> 3;               // 0..31: A row base / U row
    const int k8 = tid & 7;
    const size_t aoff = (size_t)ra * H_ + k8 * 8;
    const size_t boff = (size_t)((ra >> 3) * H_ + j0 + (ra & 7)) * H_ + k8 * 8;
    const uint32_t sa  = (uint32_t)(ra * RSB + k8 * 16);

    // Load U slice into persistent smem (once): 16 k-tiles x 32 rows x 128B, hi+lo
    for (int kt = 0; kt < 16; kt++) {
        const size_t go = boff + (size_t)kt * 64;
        *(uint4*)(sm + ST_UHI + kt * 4608 + sa) = *(const uint4*)(g_Ut_hi + go);
        *(uint4*)(sm + ST_ULO + kt * 4608 + sa) = *(const uint4*)(g_Ut_lo + go);
    }
    __syncthreads();

    const int r = lane >> 2;
    const int cc = (lane & 3) * 2;

    for (int t = 0; t < T_; t++) {
        float ci0 = 0.f, ci1 = 0.f, ci2 = 0.f, ci3 = 0.f;
        float cf0 = 0.f, cf1 = 0.f, cf2 = 0.f, cf3 = 0.f;
        float cg0 = 0.f, cg1 = 0.f, cg2 = 0.f, cg3 = 0.f;
        float co0 = 0.f, co1 = 0.f, co2 = 0.f, co3 = 0.f;

        // Prefetch xz epilogue operands early (latency hidden behind MMA loop)
        const float* xzp0 = g_xz + ((size_t)t * B_ + (m0 + r)) * G4 + j0 + cc;
        const float* xzp1 = g_xz + ((size_t)t * B_ + (m0 + r + 8)) * G4 + j0 + cc;
        float2 pzi0 = *(const float2*)(xzp0 + 0 * H_);
        float2 pzf0 = *(const float2*)(xzp0 + 1 * H_);
        float2 pzg0 = *(const float2*)(xzp0 + 2 * H_);
        float2 pzo0 = *(const float2*)(xzp0 + 3 * H_);
        float2 pzi1 = *(const float2*)(xzp1 + 0 * H_);
        float2 pzf1 = *(const float2*)(xzp1 + 1 * H_);
        float2 pzg1 = *(const float2*)(xzp1 + 2 * H_);
        float2 pzo1 = *(const float2*)(xzp1 + 3 * H_);

        if (t > 0) {
            uint4 p0, p1, p2, p3, p4, p5, p6, p7;
            // tile 0 -> regs -> buf0
            p0 = *(const uint4*)(g_h_hi + aoff);
            p1 = *(const uint4*)(g_h_hi + aoff + (size_t)32 * H_);
            p2 = *(const uint4*)(g_h_hi + aoff + (size_t)64 * H_);
            p3 = *(const uint4*)(g_h_hi + aoff + (size_t)96 * H_);
            p4 = *(const uint4*)(g_h_lo + aoff);
            p5 = *(const uint4*)(g_h_lo + aoff + (size_t)32 * H_);
            p6 = *(const uint4*)(g_h_lo + aoff + (size_t)64 * H_);
            p7 = *(const uint4*)(g_h_lo + aoff + (size_t)96 * H_);
            *(uint4*)(sm + ST_A0 + ST_AHI + sa)            = p0;
            *(uint4*)(sm + ST_A0 + ST_AHI + sa + 32 * RSB) = p1;
            *(uint4*)(sm + ST_A0 + ST_AHI + sa + 64 * RSB) = p2;
            *(uint4*)(sm + ST_A0 + ST_AHI + sa + 96 * RSB) = p3;
            *(uint4*)(sm + ST_A0 + ST_ALO + sa)            = p4;
            *(uint4*)(sm + ST_A0 + ST_ALO + sa + 32 * RSB) = p5;
            *(uint4*)(sm + ST_A0 + ST_ALO + sa + 64 * RSB) = p6;
            *(uint4*)(sm + ST_A0 + ST_ALO + sa + 96 * RSB) = p7;
            // tile 1 -> regs
            {
                const size_t koff = 64;
                p0 = *(const uint4*)(g_h_hi + aoff + koff);
                p1 = *(const uint4*)(g_h_hi + aoff + (size_t)32 * H_ + koff);
                p2 = *(const uint4*)(g_h_hi + aoff + (size_t)64 * H_ + koff);
                p3 = *(const uint4*)(g_h_hi + aoff + (size_t)96 * H_ + koff);
                p4 = *(const uint4*)(g_h_lo + aoff + koff);
                p5 = *(const uint4*)(g_h_lo + aoff + (size_t)32 * H_ + koff);
                p6 = *(const uint4*)(g_h_lo + aoff + (size_t)64 * H_ + koff);
                p7 = *(const uint4*)(g_h_lo + aoff + (size_t)96 * H_ + koff);
            }
            __syncthreads();

            for (int kt = 0; kt < 16; kt++) {
                const uint32_t ab = sb + ((kt & 1) ? ST_A1 : ST_A0);   // compute A buf
                char* cs = sm + ((kt & 1) ? ST_A0 : ST_A1);            // store A buf
                if (kt + 1 < 16) {
                    *(uint4*)(cs + ST_AHI + sa)            = p0;
                    *(uint4*)(cs + ST_AHI + sa + 32 * RSB) = p1;
                    *(uint4*)(cs + ST_AHI + sa + 64 * RSB) = p2;
                    *(uint4*)(cs + ST_AHI + sa + 96 * RSB) = p3;
                    *(uint4*)(cs + ST_ALO + sa)            = p4;
                    *(uint4*)(cs + ST_ALO + sa + 32 * RSB) = p5;
                    *(uint4*)(cs + ST_ALO + sa + 64 * RSB) = p6;
                    *(uint4*)(cs + ST_ALO + sa + 96 * RSB) = p7;
                }
                if (kt + 2 < 16) {
                    const size_t koff = (size_t)(kt + 2) * 64;
                    p0 = *(const uint4*)(g_h_hi + aoff + koff);
                    p1 = *(const uint4*)(g_h_hi + aoff + (size_t)32 * H_ + koff);
                    p2 = *(const uint4*)(g_h_hi + aoff + (size_t)64 * H_ + koff);
                    p3 = *(const uint4*)(g_h_hi + aoff + (size_t)96 * H_ + koff);
                    p4 = *(const uint4*)(g_h_lo + aoff + koff);
                    p5 = *(const uint4*)(g_h_lo + aoff + (size_t)32 * H_ + koff);
                    p6 = *(const uint4*)(g_h_lo + aoff + (size_t)64 * H_ + koff);
                    p7 = *(const uint4*)(g_h_lo + aoff + (size_t)96 * H_ + koff);
                }
                const uint32_t ub_hi = sb + ST_UHI + (uint32_t)kt * 4608 + b_off;
                const uint32_t ub_lo = sb + ST_ULO + (uint32_t)kt * 4608 + b_off;
#pragma unroll
                for (int s = 0; s < 4; s++) {
                    uint32_t ah0, ah1, ah2, ah3, al0, al1, al2, al3;
                    uint32_t b0, b1, b2, b3, d0, d1, d2, d3;
                    LDM4(ah0, ah1, ah2, ah3, ab + ST_AHI + a_off + s * 32);
                    LDM4(al0, al1, al2, al3, ab + ST_ALO + a_off + s * 32);
                    LDM4(b0, b1, b2, b3, ub_hi + s * 32);
                    LDM4(d0, d1, d2, d3, ub_lo + s * 32);
                    MMA(ci0, ci1, ci2, ci3, ah0, ah1, ah2, ah3, b0, b1);
                    MMA(ci0, ci1, ci2, ci3, ah0, ah1, ah2, ah3, d0, d1);
                    MMA(ci0, ci1, ci2, ci3, al0, al1, al2, al3, b0, b1);
                    MMA(cf0, cf1, cf2, cf3, ah0, ah1, ah2, ah3, b2, b3);
                    MMA(cf0, cf1, cf2, cf3, ah0, ah1, ah2, ah3, d2, d3);
                    MMA(cf0, cf1, cf2, cf3, al0, al1, al2, al3, b2, b3);
                    LDM4(b0, b1, b2, b3, ub_hi + 2304 + s * 32);
                    LDM4(d0, d1, d2, d3, ub_lo + 2304 + s * 32);
                    MMA(cg0, cg1, cg2, cg3, ah0, ah1, ah2, ah3, b0, b1);
                    MMA(cg0, cg1, cg2, cg3, ah0, ah1, ah2, ah3, d0, d1);
                    MMA(cg0, cg1, cg2, cg3, al0, al1, al2, al3, b0, b1);
                    MMA(co0, co1, co2, co3, ah0, ah1, ah2, ah3, b2, b3);
                    MMA(co0, co1, co2, co3, ah0, ah1, ah2, ah3, d2, d3);
                    MMA(co0, co1, co2, co3, al0, al1, al2, al3, b2, b3);
                }
                __syncthreads();
            }
        }

        // Gates + state update (prefetched xz operands)
        const int first = (t == 0);
#pragma unroll
        for (int rh = 0; rh < 2; rh++) {
            int b = m0 + r + rh * 8;
#pragma unroll
            for (int ch = 0; ch < 2; ch++) {
                int j = j0 + cc + ch;
                float zi, zf, zg, zo;
                if (rh == 0 && ch == 0) { zi = ci0 + pzi0.x; zf = cf0 + pzf0.x;
                                          zg = cg0 + pzg0.x; zo = co0 + pzo0.x; }
                else if (rh == 0)       { zi = ci1 + pzi0.y; zf = cf1 + pzf0.y;
                                          zg = cg1 + pzg0.y; zo = co1 + pzo0.y; }
                else if (ch == 0)       { zi = ci2 + pzi1.x; zf = cf2 + pzf1.x;
                                          zg = cg2 + pzg1.x; zo = co2 + pzo1.x; }
                else                    { zi = ci3 + pzi1.y; zf = cf3 + pzf1.y;
                                          zg = cg3 + pzg1.y; zo = co3 + pzo1.y; }
                float ig = fast_sigmoid(zi);
                float fg = fast_sigmoid(zf);
                float gg = tanhf(zg);
                float og = fast_sigmoid(zo);
                size_t idx = (size_t)b * H_ + j;
                float c_old = first ? 0.0f : g_c[idx];
                float cv = fg * c_old + ig * gg;
                float hv = og * tanhf(cv);
                g_c[idx] = cv;
                out[(size_t)t * B_ * H_ + idx] = hv;
                __nv_bfloat16 hi = __float2bfloat16(hv);
                g_h_hi[idx] = hi;
                g_h_lo[idx] = __float2bfloat16(hv - __bfloat162float(hi));
            }
        }

        // Grid barrier (proven): bounded spin, release/acquire fences.
        if (t + 1 < T_) {
            __syncthreads();
            if (tid == 0) {
                __threadfence();
                atomicAdd(&g_bar, 1u);
                unsigned target = (unsigned)(t + 1) * 128u;
                volatile unsigned* vb = &g_bar;
                int spins = 0;
                while (*vb < target && spins < 2000000) { spins++; __nanosleep(60); }
            }
            __syncthreads();
            __threadfence();
        }
    }
}

// ---------------------------------------------------------------------------
extern "C" void kernel_launch(void* const* d_in, const int* in_sizes, int n_in,
                              void* d_out, int out_size) {
    const float* x = (const float*)d_in[0];   // [B, T, F]
    const float* W = (const float*)d_in[1];   // [F, 4H]
    const float* U = (const float*)d_in[2];   // [H, 4H]
    const float* b = (const float*)d_in[3];   // [4H]
    float* out = (float*)d_out;               // [T, B, H]
    (void)in_sizes; (void)n_in; (void)out_size;

    cudaFuncSetAttribute(xw_mma_kernel,   cudaFuncAttributeMaxDynamicSharedMemorySize, XW_SMEM);
    cudaFuncSetAttribute(lstm_persistent, cudaFuncAttributeMaxDynamicSharedMemorySize, ST_SMEM);

    // Prep (off the serial path)
    init_bar_kernel<<<1, 1>>>();
    convx_kernel<<<16384, 256>>>(x);
    transpose_split_kernel<<<dim3(F_ / 32, G4 / 32), 256>>>(W, F_, G4, 1);
    transpose_split_kernel<<<dim3(H_ / 32, G4 / 32), 256>>>(U, H_, G4, 0);

    // Phase 1: xz = x@W + bias (tensor cores, N=64/CTA)
    xw_mma_kernel<<<dim3(64, 256), 256, XW_SMEM>>>(b);

    // Phase 2: full recurrence in ONE persistent launch (U resident in smem)
    lstm_persistent<<<128, 256, ST_SMEM>>>(out);
}

// round 17
// speedup vs baseline: 1.2186x; 1.1443x over previous
#include <cuda_runtime.h>
#include <cuda_bf16.h>
#include <math.h>
#include <stdint.h>

#define B_  128
#define T_  256
#define F_  512
#define H_  1024
#define G4  4096   // 4*H

// ---------------------------------------------------------------------------
// Scratch (static __device__; no runtime allocation)
// ---------------------------------------------------------------------------
__device__ float         g_xz[(size_t)T_ * B_ * G4];          // 537 MB fp32
__device__ float         g_c[(size_t)B_ * H_];
__device__ __nv_bfloat16 g_Ut_hi[(size_t)G4 * H_];            // U^T [4096][1024]
__device__ __nv_bfloat16 g_Ut_lo[(size_t)G4 * H_];
__device__ __nv_bfloat16 g_Wt_hi[(size_t)G4 * F_];            // W^T [4096][512]
__device__ __nv_bfloat16 g_Wt_lo[(size_t)G4 * F_];
__device__ __nv_bfloat16 g_x_hi[(size_t)B_ * T_ * F_];
__device__ __nv_bfloat16 g_x_lo[(size_t)B_ * T_ * F_];
__device__ __nv_bfloat16 g_h_hi[(size_t)B_ * H_];
__device__ __nv_bfloat16 g_h_lo[(size_t)B_ * H_];
__device__ unsigned      g_bar;

__device__ __forceinline__ float fast_sigmoid(float z) {
    return 1.0f / (1.0f + __expf(-z));
}
__device__ __forceinline__ uint32_t smem_u32(const void* p) {
    uint32_t a;
    asm("{ .reg .u64 t; cvta.to.shared.u64 t, %1; cvt.u32.u64 %0, t; }" : "=r"(a) : "l"(p));
    return a;
}

// All-scalar ldmatrix / mma macros (asm operands must be scalars, never arrays).
#define LDM4(r0, r1, r2, r3, addr)                                            \
    asm volatile("ldmatrix.sync.aligned.m8n8.x4.shared.b16 {%0,%1,%2,%3}, [%4];" \
                 : "=r"(r0), "=r"(r1), "=r"(r2), "=r"(r3) : "r"(addr))
#define MMA(c0, c1, c2, c3, a0, a1, a2, a3, b0, b1)                           \
    asm volatile("mma.sync.aligned.m16n8k16.row.col.f32.bf16.bf16.f32 "       \
                 "{%0,%1,%2,%3}, {%4,%5,%6,%7}, {%8,%9}, {%0,%1,%2,%3};"      \
                 : "+f"(c0), "+f"(c1), "+f"(c2), "+f"(c3)                     \
                 : "r"(a0), "r"(a1), "r"(a2), "r"(a3), "r"(b0), "r"(b1))

// smem tile: 64 bf16/row padded to 144 B -> 8 consecutive rows hit 8 distinct
// 16B banks (144 mod 128 = 16) => conflict-free ldmatrix and STS.
#define RSB   144

// ---- xw kernel smem layout (single buffer, N=64): 55296 B dynamic ----
#define XW_AHI  0
#define XW_ALO  18432
#define XW_BHI  36864
#define XW_BLO  46080
#define XW_SMEM 55296

// ---- step kernel: two K-halves, each with R12 layout; 92160 B dynamic ----
#define HB      46080      // per-half region stride
#define SA_HI   0
#define SA_LO   18432
#define SB_HI   36864
#define SB_LO   41472
#define EXCH    46080      // reduction exchange area = half-1 A region (16 KB used)
#define ST_SMEM (2 * HB)

// ---------------------------------------------------------------------------
// Prep kernels
// ---------------------------------------------------------------------------
__global__ void init_bar_kernel() { g_bar = 0u; }

__global__ void convx_kernel(const float* __restrict__ x) {
    size_t i = ((size_t)blockIdx.x * 256 + threadIdx.x) * 4;   // grid 16384
    float4 v = *(const float4*)(x + i);
    float vv[4] = {v.x, v.y, v.z, v.w};
#pragma unroll
    for (int m = 0; m < 4; m++) {
        __nv_bfloat16 hi = __float2bfloat16(vv[m]);
        g_x_hi[i + m] = hi;
        g_x_lo[i + m] = __float2bfloat16(vv[m] - __bfloat162float(hi));
    }
}

// in [K][N] fp32 -> (which ? g_Wt : g_Ut) hi/lo [N][K] bf16
__global__ __launch_bounds__(256) void transpose_split_kernel(const float* __restrict__ in,
                                                              int K, int N, int which) {
    __nv_bfloat16* ohi = which ? g_Wt_hi : g_Ut_hi;
    __nv_bfloat16* olo = which ? g_Wt_lo : g_Ut_lo;
    __shared__ float ts[32][33];
    int k0 = blockIdx.x * 32, n0 = blockIdx.y * 32;
    int r = threadIdx.x >> 5, c = threadIdx.x & 31;
#pragma unroll
    for (int i = 0; i < 4; i++)
        ts[r + i * 8][c] = in[(size_t)(k0 + r + i * 8) * N + n0 + c];
    __syncthreads();
#pragma unroll
    for (int i = 0; i < 4; i++) {
        int n = n0 + r + i * 8;
        float v = ts[c][r + i * 8];
        __nv_bfloat16 hi = __float2bfloat16(v);
        ohi[(size_t)n * K + k0 + c] = hi;
        olo[(size_t)n * K + k0 + c] = __float2bfloat16(v - __bfloat162float(hi));
    }
}

// ---------------------------------------------------------------------------
// xw MMA kernel (R15-proven): g_xz[t][b][n] = x_t @ W + bias.
// Grid (64, 256) = (n-tile, t). M=128, N=64/CTA, K=512.
// ---------------------------------------------------------------------------
__global__ __launch_bounds__(256) void xw_mma_kernel(const float* __restrict__ bias) {
    extern __shared__ __align__(16) char sm[];
    const int tid = threadIdx.x, wid = tid >> 5, lane = tid & 31;
    const int n0 = blockIdx.x * 64;
    const int t  = blockIdx.y;
    const uint32_t sb = smem_u32(sm);
    const int m0 = wid * 16;

    const uint32_t a_off = (uint32_t)((m0 + (lane & 15)) * RSB + (lane >> 4) * 16);
    const uint32_t b_off = (uint32_t)((((lane >> 4) & 1) * 8 + (lane & 7)) * RSB
                                      + ((lane >> 3) & 1) * 16);

    float ci0=0.f,ci1=0.f,ci2=0.f,ci3=0.f, cf0=0.f,cf1=0.f,cf2=0.f,cf3=0.f;
    float cg0=0.f,cg1=0.f,cg2=0.f,cg3=0.f, co0=0.f,co1=0.f,co2=0.f,co3=0.f;
    float ki0=0.f,ki1=0.f,ki2=0.f,ki3=0.f, kf0=0.f,kf1=0.f,kf2=0.f,kf3=0.f;
    float kg0=0.f,kg1=0.f,kg2=0.f,kg3=0.f, ko0=0.f,ko1=0.f,ko2=0.f,ko3=0.f;

    const int ra = tid >> 3;
    const int k8 = tid & 7;
    const size_t aoff = ((size_t)ra * T_ + t) * F_ + k8 * 8;
    const size_t arow = (size_t)32 * T_ * F_;
    const size_t boffA = (size_t)(n0 + ra) * F_ + k8 * 8;
    const size_t boffB = (size_t)(n0 + 32 + ra) * F_ + k8 * 8;
    const uint32_t sa  = (uint32_t)(ra * RSB + k8 * 16);

    uint4 p0, p1, p2, p3, p4, p5, p6, p7, q0, q1, q2, q3;
    p0 = *(const uint4*)(g_x_hi + aoff);
    p1 = *(const uint4*)(g_x_hi + aoff + arow);
    p2 = *(const uint4*)(g_x_hi + aoff + 2 * arow);
    p3 = *(const uint4*)(g_x_hi + aoff + 3 * arow);
    p4 = *(const uint4*)(g_x_lo + aoff);
    p5 = *(const uint4*)(g_x_lo + aoff + arow);
    p6 = *(const uint4*)(g_x_lo + aoff + 2 * arow);
    p7 = *(const uint4*)(g_x_lo + aoff + 3 * arow);
    q0 = *(const uint4*)(g_Wt_hi + boffA);
    q1 = *(const uint4*)(g_Wt_hi + boffB);
    q2 = *(const uint4*)(g_Wt_lo + boffA);
    q3 = *(const uint4*)(g_Wt_lo + boffB);

    for (int kt = 0; kt < 8; kt++) {
        __syncthreads();
        *(uint4*)(sm + XW_AHI + sa)            = p0;
        *(uint4*)(sm + XW_AHI + sa + 32 * RSB) = p1;
        *(uint4*)(sm + XW_AHI + sa + 64 * RSB) = p2;
        *(uint4*)(sm + XW_AHI + sa + 96 * RSB) = p3;
        *(uint4*)(sm + XW_ALO + sa)            = p4;
        *(uint4*)(sm + XW_ALO + sa + 32 * RSB) = p5;
        *(uint4*)(sm + XW_ALO + sa + 64 * RSB) = p6;
        *(uint4*)(sm + XW_ALO + sa + 96 * RSB) = p7;
        *(uint4*)(sm + XW_BHI + sa)            = q0;
        *(uint4*)(sm + XW_BHI + sa + 32 * RSB) = q1;
        *(uint4*)(sm + XW_BLO + sa)            = q2;
        *(uint4*)(sm + XW_BLO + sa + 32 * RSB) = q3;
        __syncthreads();
        if (kt + 1 < 8) {
            const size_t koff = (size_t)(kt + 1) * 64;
            p0 = *(const uint4*)(g_x_hi + aoff + koff);
            p1 = *(const uint4*)(g_x_hi + aoff + arow + koff);
            p2 = *(const uint4*)(g_x_hi + aoff + 2 * arow + koff);
            p3 = *(const uint4*)(g_x_hi + aoff + 3 * arow + koff);
            p4 = *(const uint4*)(g_x_lo + aoff + koff);
            p5 = *(const uint4*)(g_x_lo + aoff + arow + koff);
            p6 = *(const uint4*)(g_x_lo + aoff + 2 * arow + koff);
            p7 = *(const uint4*)(g_x_lo + aoff + 3 * arow + koff);
            q0 = *(const uint4*)(g_Wt_hi + boffA + koff);
            q1 = *(const uint4*)(g_Wt_hi + boffB + koff);
            q2 = *(const uint4*)(g_Wt_lo + boffA + koff);
            q3 = *(const uint4*)(g_Wt_lo + boffB + koff);
        }
#pragma unroll
        for (int s = 0; s < 4; s++) {
            uint32_t ah0, ah1, ah2, ah3, al0, al1, al2, al3;
            uint32_t b0, b1, b2, b3, d0, d1, d2, d3;
            LDM4(ah0, ah1, ah2, ah3, sb + XW_AHI + a_off + s * 32);
            LDM4(al0, al1, al2, al3, sb + XW_ALO + a_off + s * 32);
            LDM4(b0, b1, b2, b3, sb + XW_BHI + b_off + s * 32);
            LDM4(d0, d1, d2, d3, sb + XW_BLO + b_off + s * 32);
            MMA(ci0, ci1, ci2, ci3, ah0, ah1, ah2, ah3, b0, b1);
            MMA(ci0, ci1, ci2, ci3, ah0, ah1, ah2, ah3, d0, d1);
            MMA(ci0, ci1, ci2, ci3, al0, al1, al2, al3, b0, b1);
            MMA(cf0, cf1, cf2, cf3, ah0, ah1, ah2, ah3, b2, b3);
            MMA(cf0, cf1, cf2, cf3, ah0, ah1, ah2, ah3, d2, d3);
            MMA(cf0, cf1, cf2, cf3, al0, al1, al2, al3, b2, b3);
            LDM4(b0, b1, b2, b3, sb + XW_BHI + b_off + 2304 + s * 32);
            LDM4(d0, d1, d2, d3, sb + XW_BLO + b_off + 2304 + s * 32);
            MMA(cg0, cg1, cg2, cg3, ah0, ah1, ah2, ah3, b0, b1);
            MMA(cg0, cg1, cg2, cg3, ah0, ah1, ah2, ah3, d0, d1);
            MMA(cg0, cg1, cg2, cg3, al0, al1, al2, al3, b0, b1);
            MMA(co0, co1, co2, co3, ah0, ah1, ah2, ah3, b2, b3);
            MMA(co0, co1, co2, co3, ah0, ah1, ah2, ah3, d2, d3);
            MMA(co0, co1, co2, co3, al0, al1, al2, al3, b2, b3);
            LDM4(b0, b1, b2, b3, sb + XW_BHI + b_off + 4608 + s * 32);
            LDM4(d0, d1, d2, d3, sb + XW_BLO + b_off + 4608 + s * 32);
            MMA(ki0, ki1, ki2, ki3, ah0, ah1, ah2, ah3, b0, b1);
            MMA(ki0, ki1, ki2, ki3, ah0, ah1, ah2, ah3, d0, d1);
            MMA(ki0, ki1, ki2, ki3, al0, al1, al2, al3, b0, b1);
            MMA(kf0, kf1, kf2, kf3, ah0, ah1, ah2, ah3, b2, b3);
            MMA(kf0, kf1, kf2, kf3, ah0, ah1, ah2, ah3, d2, d3);
            MMA(kf0, kf1, kf2, kf3, al0, al1, al2, al3, b2, b3);
            LDM4(b0, b1, b2, b3, sb + XW_BHI + b_off + 6912 + s * 32);
            LDM4(d0, d1, d2, d3, sb + XW_BLO + b_off + 6912 + s * 32);
            MMA(kg0, kg1, kg2, kg3, ah0, ah1, ah2, ah3, b0, b1);
            MMA(kg0, kg1, kg2, kg3, ah0, ah1, ah2, ah3, d0, d1);
            MMA(kg0, kg1, kg2, kg3, al0, al1, al2, al3, b0, b1);
            MMA(ko0, ko1, ko2, ko3, ah0, ah1, ah2, ah3, b2, b3);
            MMA(ko0, ko1, ko2, ko3, ah0, ah1, ah2, ah3, d2, d3);
            MMA(ko0, ko1, ko2, ko3, al0, al1, al2, al3, b2, b3);
        }
    }

    const int r = lane >> 2;
    const int cc = (lane & 3) * 2;
    float2 bv0 = *(const float2*)(bias + n0 + cc);
    float2 bv1 = *(const float2*)(bias + n0 + 8 + cc);
    float2 bv2 = *(const float2*)(bias + n0 + 16 + cc);
    float2 bv3 = *(const float2*)(bias + n0 + 24 + cc);
    float2 bv4 = *(const float2*)(bias + n0 + 32 + cc);
    float2 bv5 = *(const float2*)(bias + n0 + 40 + cc);
    float2 bv6 = *(const float2*)(bias + n0 + 48 + cc);
    float2 bv7 = *(const float2*)(bias + n0 + 56 + cc);
#pragma unroll
    for (int rh = 0; rh < 2; rh++) {
        int b = m0 + r + rh * 8;
        float* dst = g_xz + ((size_t)t * B_ + b) * G4 + n0;
        float vi0 = rh ? ci2 : ci0, vi1 = rh ? ci3 : ci1;
        float vf0 = rh ? cf2 : cf0, vf1 = rh ? cf3 : cf1;
        float vg0 = rh ? cg2 : cg0, vg1 = rh ? cg3 : cg1;
        float vo0 = rh ? co2 : co0, vo1 = rh ? co3 : co1;
        float wi0 = rh ? ki2 : ki0, wi1 = rh ? ki3 : ki1;
        float wf0 = rh ? kf2 : kf0, wf1 = rh ? kf3 : kf1;
        float wg0 = rh ? kg2 : kg0, wg1 = rh ? kg3 : kg1;
        float wo0 = rh ? ko2 : ko0, wo1 = rh ? ko3 : ko1;
        *(float2*)(dst + cc)      = make_float2(vi0 + bv0.x, vi1 + bv0.y);
        *(float2*)(dst + 8 + cc)  = make_float2(vf0 + bv1.x, vf1 + bv1.y);
        *(float2*)(dst + 16 + cc) = make_float2(vg0 + bv2.x, vg1 + bv2.y);
        *(float2*)(dst + 24 + cc) = make_float2(vo0 + bv3.x, vo1 + bv3.y);
        *(float2*)(dst + 32 + cc) = make_float2(wi0 + bv4.x, wi1 + bv4.y);
        *(float2*)(dst + 40 + cc) = make_float2(wf0 + bv5.x, wf1 + bv5.y);
        *(float2*)(dst + 48 + cc) = make_float2(wg0 + bv6.x, wg1 + bv6.y);
        *(float2*)(dst + 56 + cc) = make_float2(wo0 + bv7.x, wo1 + bv7.y);
    }
}

// ---------------------------------------------------------------------------
// Persistent recurrence: 128 CTAs x 512 threads (16 warps), intra-CTA split-K.
// Warps 0-7: K [0,512); warps 8-15: K [512,1024). Each half runs the proven
// R12 single-buffer pipeline on its own smem region; fp32 reduction at end.
// ---------------------------------------------------------------------------
__global__ __launch_bounds__(512, 1) void lstm_persistent(float* __restrict__ out) {
    extern __shared__ __align__(16) char sm[];
    const int tid = threadIdx.x, wid = tid >> 5, lane = tid & 31;
    const int j0 = blockIdx.x * 8;
    const int hh = wid >> 3;                  // K-half: 0 or 1
    const int mw = (wid & 7) * 16;            // m-tile within half
    char* hs = sm + hh * HB;                  // this half's smem region
    const uint32_t hsb = smem_u32(sm) + (uint32_t)hh * HB;

    const uint32_t a_off = (uint32_t)((mw + (lane & 15)) * RSB + (lane >> 4) * 16);
    const uint32_t b_off = (uint32_t)((((lane >> 4) & 1) * 8 + (lane & 7)) * RSB
                                      + ((lane >> 3) & 1) * 16);

    // Loader role: ts = tid within half (0..255), same mapping as R12.
    const int ts = tid & 255;
    const int ra = ts >> 3;                   // 0..31
    const int k8 = ts & 7;
    const size_t kbase = (size_t)hh * 512;
    const size_t aoff = (size_t)ra * H_ + kbase + k8 * 8;
    const size_t boff = (size_t)((ra >> 3) * H_ + j0 + (ra & 7)) * H_ + kbase + k8 * 8;
    const uint32_t sa  = (uint32_t)(ra * RSB + k8 * 16);

    const int r = lane >> 2;
    const int cc = (lane & 3) * 2;

    for (int t = 0; t < T_; t++) {
        float ci0 = 0.f, ci1 = 0.f, ci2 = 0.f, ci3 = 0.f;
        float cf0 = 0.f, cf1 = 0.f, cf2 = 0.f, cf3 = 0.f;
        float cg0 = 0.f, cg1 = 0.f, cg2 = 0.f, cg3 = 0.f;
        float co0 = 0.f, co1 = 0.f, co2 = 0.f, co3 = 0.f;

        // xz epilogue operands: prefetched only by half 0 (the finalizers).
        float2 pzi0, pzf0, pzg0, pzo0, pzi1, pzf1, pzg1, pzo1;
        if (hh == 0) {
            const float* xzp0 = g_xz + ((size_t)t * B_ + (mw + r)) * G4 + j0 + cc;
            const float* xzp1 = g_xz + ((size_t)t * B_ + (mw + r + 8)) * G4 + j0 + cc;
            pzi0 = *(const float2*)(xzp0 + 0 * H_);
            pzf0 = *(const float2*)(xzp0 + 1 * H_);
            pzg0 = *(const float2*)(xzp0 + 2 * H_);
            pzo0 = *(const float2*)(xzp0 + 3 * H_);
            pzi1 = *(const float2*)(xzp1 + 0 * H_);
            pzf1 = *(const float2*)(xzp1 + 1 * H_);
            pzg1 = *(const float2*)(xzp1 + 2 * H_);
            pzo1 = *(const float2*)(xzp1 + 3 * H_);
        }

        if (t > 0) {
            uint4 p0, p1, p2, p3, p4, p5, p6, p7, q0, q1;
            // k-tile 0 of this half -> regs
            p0 = *(const uint4*)(g_h_hi + aoff);
            p1 = *(const uint4*)(g_h_hi + aoff + (size_t)32 * H_);
            p2 = *(const uint4*)(g_h_hi + aoff + (size_t)64 * H_);
            p3 = *(const uint4*)(g_h_hi + aoff + (size_t)96 * H_);
            p4 = *(const uint4*)(g_h_lo + aoff);
            p5 = *(const uint4*)(g_h_lo + aoff + (size_t)32 * H_);
            p6 = *(const uint4*)(g_h_lo + aoff + (size_t)64 * H_);
            p7 = *(const uint4*)(g_h_lo + aoff + (size_t)96 * H_);
            q0 = *(const uint4*)(g_Ut_hi + boff);
            q1 = *(const uint4*)(g_Ut_lo + boff);

            for (int kt = 0; kt < 8; kt++) {
                __syncthreads();
                *(uint4*)(hs + SA_HI + sa)            = p0;
                *(uint4*)(hs + SA_HI + sa + 32 * RSB) = p1;
                *(uint4*)(hs + SA_HI + sa + 64 * RSB) = p2;
                *(uint4*)(hs + SA_HI + sa + 96 * RSB) = p3;
                *(uint4*)(hs + SA_LO + sa)            = p4;
                *(uint4*)(hs + SA_LO + sa + 32 * RSB) = p5;
                *(uint4*)(hs + SA_LO + sa + 64 * RSB) = p6;
                *(uint4*)(hs + SA_LO + sa + 96 * RSB) = p7;
                *(uint4*)(hs + SB_HI + sa)            = q0;
                *(uint4*)(hs + SB_LO + sa)            = q1;
                __syncthreads();
                if (kt + 1 < 8) {
                    const size_t koff = (size_t)(kt + 1) * 64;
                    p0 = *(const uint4*)(g_h_hi + aoff + koff);
                    p1 = *(const uint4*)(g_h_hi + aoff + (size_t)32 * H_ + koff);
                    p2 = *(const uint4*)(g_h_hi + aoff + (size_t)64 * H_ + koff);
                    p3 = *(const uint4*)(g_h_hi + aoff + (size_t)96 * H_ + koff);
                    p4 = *(const uint4*)(g_h_lo + aoff + koff);
                    p5 = *(const uint4*)(g_h_lo + aoff + (size_t)32 * H_ + koff);
                    p6 = *(const uint4*)(g_h_lo + aoff + (size_t)64 * H_ + koff);
                    p7 = *(const uint4*)(g_h_lo + aoff + (size_t)96 * H_ + koff);
                    q0 = *(const uint4*)(g_Ut_hi + boff + koff);
                    q1 = *(const uint4*)(g_Ut_lo + boff + koff);
                }
#pragma unroll
                for (int s = 0; s < 4; s++) {
                    uint32_t ah0, ah1, ah2, ah3, al0, al1, al2, al3;
                    uint32_t b0, b1, b2, b3, d0, d1, d2, d3;
                    LDM4(ah0, ah1, ah2, ah3, hsb + SA_HI + a_off + s * 32);
                    LDM4(al0, al1, al2, al3, hsb + SA_LO + a_off + s * 32);
                    LDM4(b0, b1, b2, b3, hsb + SB_HI + b_off + s * 32);
                    LDM4(d0, d1, d2, d3, hsb + SB_LO + b_off + s * 32);
                    MMA(ci0, ci1, ci2, ci3, ah0, ah1, ah2, ah3, b0, b1);
                    MMA(ci0, ci1, ci2, ci3, ah0, ah1, ah2, ah3, d0, d1);
                    MMA(ci0, ci1, ci2, ci3, al0, al1, al2, al3, b0, b1);
                    MMA(cf0, cf1, cf2, cf3, ah0, ah1, ah2, ah3, b2, b3);
                    MMA(cf0, cf1, cf2, cf3, ah0, ah1, ah2, ah3, d2, d3);
                    MMA(cf0, cf1, cf2, cf3, al0, al1, al2, al3, b2, b3);
                    LDM4(b0, b1, b2, b3, hsb + SB_HI + b_off + 16 * RSB + s * 32);
                    LDM4(d0, d1, d2, d3, hsb + SB_LO + b_off + 16 * RSB + s * 32);
                    MMA(cg0, cg1, cg2, cg3, ah0, ah1, ah2, ah3, b0, b1);
                    MMA(cg0, cg1, cg2, cg3, ah0, ah1, ah2, ah3, d0, d1);
                    MMA(cg0, cg1, cg2, cg3, al0, al1, al2, al3, b0, b1);
                    MMA(co0, co1, co2, co3, ah0, ah1, ah2, ah3, b2, b3);
                    MMA(co0, co1, co2, co3, ah0, ah1, ah2, ah3, d2, d3);
                    MMA(co0, co1, co2, co3, al0, al1, al2, al3, b2, b3);
                }
            }

            // Reduction: half-1 -> smem -> half-0 adds. Conflict-free float4
            // pattern: addr = EXCH + q*4096 + ts*16.
            __syncthreads();
            if (hh == 1) {
                *(float4*)(sm + EXCH + 0 * 4096 + ts * 16) = make_float4(ci0, ci1, ci2, ci3);
                *(float4*)(sm + EXCH + 1 * 4096 + ts * 16) = make_float4(cf0, cf1, cf2, cf3);
                *(float4*)(sm + EXCH + 2 * 4096 + ts * 16) = make_float4(cg0, cg1, cg2, cg3);
                *(float4*)(sm + EXCH + 3 * 4096 + ts * 16) = make_float4(co0, co1, co2, co3);
            }
            __syncthreads();
            if (hh == 0) {
                float4 vi = *(const float4*)(sm + EXCH + 0 * 4096 + ts * 16);
                float4 vf = *(const float4*)(sm + EXCH + 1 * 4096 + ts * 16);
                float4 vg = *(const float4*)(sm + EXCH + 2 * 4096 + ts * 16);
                float4 vo = *(const float4*)(sm + EXCH + 3 * 4096 + ts * 16);
                ci0 += vi.x; ci1 += vi.y; ci2 += vi.z; ci3 += vi.w;
                cf0 += vf.x; cf1 += vf.y; cf2 += vf.z; cf3 += vf.w;
                cg0 += vg.x; cg1 += vg.y; cg2 += vg.z; cg3 += vg.w;
                co0 += vo.x; co1 += vo.y; co2 += vo.z; co3 += vo.w;
            }
        }

        // Gates + state update (half-0 threads only; mapping identical to R12)
        if (hh == 0) {
            const int first = (t == 0);
#pragma unroll
            for (int rh = 0; rh < 2; rh++) {
                int b = mw + r + rh * 8;
#pragma unroll
                for (int ch = 0; ch < 2; ch++) {
                    int j = j0 + cc + ch;
                    float zi, zf, zg, zo;
                    if (rh == 0 && ch == 0) { zi = ci0 + pzi0.x; zf = cf0 + pzf0.x;
                                              zg = cg0 + pzg0.x; zo = co0 + pzo0.x; }
                    else if (rh == 0)       { zi = ci1 + pzi0.y; zf = cf1 + pzf0.y;
                                              zg = cg1 + pzg0.y; zo = co1 + pzo0.y; }
                    else if (ch == 0)       { zi = ci2 + pzi1.x; zf = cf2 + pzf1.x;
                                              zg = cg2 + pzg1.x; zo = co2 + pzo1.x; }
                    else                    { zi = ci3 + pzi1.y; zf = cf3 + pzf1.y;
                                              zg = cg3 + pzg1.y; zo = co3 + pzo1.y; }
                    float ig = fast_sigmoid(zi);
                    float fg = fast_sigmoid(zf);
                    float gg = tanhf(zg);
                    float og = fast_sigmoid(zo);
                    size_t idx = (size_t)b * H_ + j;
                    float c_old = first ? 0.0f : g_c[idx];
                    float cv = fg * c_old + ig * gg;
                    float hv = og * tanhf(cv);
                    g_c[idx] = cv;
                    out[(size_t)t * B_ * H_ + idx] = hv;
                    __nv_bfloat16 hi = __float2bfloat16(hv);
                    g_h_hi[idx] = hi;
                    g_h_lo[idx] = __float2bfloat16(hv - __bfloat162float(hi));
                }
            }
        }

        // Grid barrier (proven): bounded spin, release/acquire fences.
        if (t + 1 < T_) {
            __syncthreads();
            if (tid == 0) {
                __threadfence();
                atomicAdd(&g_bar, 1u);
                unsigned target = (unsigned)(t + 1) * 128u;
                volatile unsigned* vb = &g_bar;
                int spins = 0;
                while (*vb < target && spins < 2000000) { spins++; __nanosleep(60); }
            }
            __syncthreads();
            __threadfence();
        }
    }
}

// ---------------------------------------------------------------------------
extern "C" void kernel_launch(void* const* d_in, const int* in_sizes, int n_in,
                              void* d_out, int out_size) {
    const float* x = (const float*)d_in[0];   // [B, T, F]
    const float* W = (const float*)d_in[1];   // [F, 4H]
    const float* U = (const float*)d_in[2];   // [H, 4H]
    const float* b = (const float*)d_in[3];   // [4H]
    float* out = (float*)d_out;               // [T, B, H]
    (void)in_sizes; (void)n_in; (void)out_size;

    cudaFuncSetAttribute(xw_mma_kernel,   cudaFuncAttributeMaxDynamicSharedMemorySize, XW_SMEM);
    cudaFuncSetAttribute(lstm_persistent, cudaFuncAttributeMaxDynamicSharedMemorySize, ST_SMEM);

    // Prep (off the serial path)
    init_bar_kernel<<<1, 1>>>();
    convx_kernel<<<16384, 256>>>(x);
    transpose_split_kernel<<<dim3(F_ / 32, G4 / 32), 256>>>(W, F_, G4, 1);
    transpose_split_kernel<<<dim3(H_ / 32, G4 / 32), 256>>>(U, H_, G4, 0);

    // Phase 1: xz = x@W + bias (tensor cores, N=64/CTA)
    xw_mma_kernel<<<dim3(64, 256), 256, XW_SMEM>>>(b);

    // Phase 2: full recurrence in ONE persistent launch (intra-CTA split-K)
    lstm_persistent<<<128, 512, ST_SMEM>>>(out);
}